// round 2
// baseline (speedup 1.0000x reference)
#include <cuda_runtime.h>
#include <math.h>

// Problem constants
#define BB 16
#define TT 1024
#define DD 512
#define MTOT (BB * TT)                  // 16384 rows total
#define SCALE 0.04419417382415922f      // 1/sqrt(512)

// ---------------- scratch (device globals; allocation-free) ----------------
// Aliased buffers to keep static footprint at 160 MB:
//   g_Q : Q projections, then reused for attention output (val)
//   g_K : K projections, then reused for conv1+relu output (h)
//   g_V : V projections, then reused for enhanced
//   g_S : scores -> probs in place
__device__ float g_Q[BB * TT * DD];     // 32 MB
__device__ float g_K[BB * TT * DD];     // 32 MB
__device__ float g_V[BB * TT * DD];     // 32 MB
__device__ float g_S[BB * TT * TT];     // 64 MB

#define g_val g_Q
#define g_h   g_K
#define g_enh g_V

// ---------------- GEMM machinery: 128x128 tile, 8x8 micro, BK=8 -----------
// 256 threads (16x16 micro-tile grid). Double-buffered smem, register-staged
// global loads: one __syncthreads per K-step, loads overlap compute.

__device__ __forceinline__ float4 ldA(const float* __restrict__ A, int lda,
                                      int m0, int k0, int tid) {
    int lr = tid >> 1, lc = (tid & 1) * 4;
    return *reinterpret_cast<const float4*>(&A[(size_t)(m0 + lr) * lda + k0 + lc]);
}
__device__ __forceinline__ void stAT(float* As, float4 v, int tid) {
    int lr = tid >> 1, lc = (tid & 1) * 4;
    As[(lc + 0) * 128 + lr] = v.x;
    As[(lc + 1) * 128 + lr] = v.y;
    As[(lc + 2) * 128 + lr] = v.z;
    As[(lc + 3) * 128 + lr] = v.w;
}
__device__ __forceinline__ float4 ldB_nn(const float* __restrict__ Bm, int ldb,
                                         int k0, int n0, int tid) {
    int lr = tid >> 5, lc = (tid & 31) * 4;
    return *reinterpret_cast<const float4*>(&Bm[(size_t)(k0 + lr) * ldb + n0 + lc]);
}
__device__ __forceinline__ void stB_nn(float* Bs, float4 v, int tid) {
    int lr = tid >> 5, lc = (tid & 31) * 4;
    *reinterpret_cast<float4*>(&Bs[lr * 128 + lc]) = v;
}
__device__ __forceinline__ float4 ldB_nt(const float* __restrict__ Bm, int ldb,
                                         int n0, int k0, int tid) {
    int lr = tid >> 1, lc = (tid & 1) * 4;
    return *reinterpret_cast<const float4*>(&Bm[(size_t)(n0 + lr) * ldb + k0 + lc]);
}

__device__ __forceinline__ void mmac(const float* As, const float* Bs,
                                     float acc[8][8], int ty, int tx) {
#pragma unroll
    for (int k = 0; k < 8; k++) {
        float4 a0 = *reinterpret_cast<const float4*>(&As[k * 128 + ty * 8]);
        float4 a1 = *reinterpret_cast<const float4*>(&As[k * 128 + ty * 8 + 4]);
        float4 b0 = *reinterpret_cast<const float4*>(&Bs[k * 128 + tx * 8]);
        float4 b1 = *reinterpret_cast<const float4*>(&Bs[k * 128 + tx * 8 + 4]);
        float a[8] = {a0.x, a0.y, a0.z, a0.w, a1.x, a1.y, a1.z, a1.w};
        float b[8] = {b0.x, b0.y, b0.z, b0.w, b1.x, b1.y, b1.z, b1.w};
#pragma unroll
        for (int i = 0; i < 8; i++)
#pragma unroll
            for (int j = 0; j < 8; j++)
                acc[i][j] = fmaf(a[i], b[j], acc[i][j]);
    }
}

__device__ __forceinline__ int vlen_of(const int* __restrict__ vl, int b) {
    // int64 vs int32 detection: v_len values are in [1,1024], so word 1 is the
    // high half (0) iff the array is little-endian int64.
    int stride = (vl[1] == 0) ? 2 : 1;
    return vl[b * stride];
}

// Double-buffered mainloop for plain NN GEMMs (A row-major, B row-major K x N)
#define GEMM_NN_LOOP(Aptr, lda, Bptr, ldb, KTOT)                               \
    do {                                                                       \
        float4 ra = ldA(Aptr, lda, m0, 0, tid);                                \
        float4 rb = ldB_nn(Bptr, ldb, 0, n0, tid);                             \
        stAT(As[0], ra, tid);                                                  \
        stB_nn(Bs[0], rb, tid);                                                \
        __syncthreads();                                                       \
        const int KT = (KTOT) / 8;                                             \
        for (int kt = 0; kt < KT; kt++) {                                      \
            int cur = kt & 1;                                                  \
            if (kt + 1 < KT) {                                                 \
                ra = ldA(Aptr, lda, m0, (kt + 1) * 8, tid);                    \
                rb = ldB_nn(Bptr, ldb, (kt + 1) * 8, n0, tid);                 \
            }                                                                  \
            mmac(As[cur], Bs[cur], acc, ty, tx);                               \
            if (kt + 1 < KT) {                                                 \
                stAT(As[cur ^ 1], ra, tid);                                    \
                stB_nn(Bs[cur ^ 1], rb, tid);                                  \
            }                                                                  \
            __syncthreads();                                                   \
        }                                                                      \
    } while (0)

// ---------------- 1) QKV projections: C = A @ W + bias --------------------
__global__ __launch_bounds__(256)
void proj_kernel(const float* __restrict__ A, const float* __restrict__ W,
                 const float* __restrict__ bias, float* __restrict__ C) {
    __shared__ __align__(16) float As[2][8 * 128];
    __shared__ __align__(16) float Bs[2][8 * 128];
    int tid = threadIdx.x, tx = tid % 16, ty = tid / 16;
    int m0 = blockIdx.y * 128, n0 = blockIdx.x * 128;
    float acc[8][8] = {};
    GEMM_NN_LOOP(A, DD, W, DD, DD);
    float bb[8];
#pragma unroll
    for (int j = 0; j < 8; j++) bb[j] = bias[n0 + tx * 8 + j];
#pragma unroll
    for (int i = 0; i < 8; i++) {
        size_t base = (size_t)(m0 + ty * 8 + i) * DD + n0 + tx * 8;
#pragma unroll
        for (int j = 0; j < 8; j++) C[base + j] = acc[i][j] + bb[j];
    }
}

// ---------------- 2) scores: S[b] = (Q[b] @ K[b]^T) * scale ----------------
__global__ __launch_bounds__(256)
void scores_kernel() {
    __shared__ __align__(16) float As[2][8 * 128];
    __shared__ __align__(16) float Bs[2][8 * 128];
    int tid = threadIdx.x, tx = tid % 16, ty = tid / 16;
    int b = blockIdx.z;
    int m0 = blockIdx.y * 128, n0 = blockIdx.x * 128;
    const float* A  = g_Q + (size_t)b * TT * DD;
    const float* Bm = g_K + (size_t)b * TT * DD;
    float acc[8][8] = {};
    {
        float4 ra = ldA(A, DD, m0, 0, tid);
        float4 rb = ldB_nt(Bm, DD, n0, 0, tid);
        stAT(As[0], ra, tid);
        stAT(Bs[0], rb, tid);     // NT B-tile stores transposed like A
        __syncthreads();
        const int KT = DD / 8;
        for (int kt = 0; kt < KT; kt++) {
            int cur = kt & 1;
            if (kt + 1 < KT) {
                ra = ldA(A, DD, m0, (kt + 1) * 8, tid);
                rb = ldB_nt(Bm, DD, n0, (kt + 1) * 8, tid);
            }
            mmac(As[cur], Bs[cur], acc, ty, tx);
            if (kt + 1 < KT) {
                stAT(As[cur ^ 1], ra, tid);
                stAT(Bs[cur ^ 1], rb, tid);
            }
            __syncthreads();
        }
    }
    float* C = g_S + (size_t)b * TT * TT;
#pragma unroll
    for (int i = 0; i < 8; i++) {
        size_t base = (size_t)(m0 + ty * 8 + i) * TT + n0 + tx * 8;
#pragma unroll
        for (int j = 0; j < 8; j++) C[base + j] = acc[i][j] * SCALE;
    }
}

// ---------------- 3) masked softmax over keys (in place on g_S) ------------
__global__ __launch_bounds__(256)
void softmax_kernel(const int* __restrict__ vl) {
    __shared__ float red[8];
    int row = blockIdx.x;           // 0..16383
    int b = row >> 10;
    int L = vlen_of(vl, b);
    float* S = g_S + (size_t)row * TT;
    int tid = threadIdx.x;
    int lane = tid & 31, wid = tid >> 5;
    int k0 = tid * 4;
    float4 v = *reinterpret_cast<float4*>(&S[k0]);
    float xs[4] = {v.x, v.y, v.z, v.w};
    float m = -3.4e38f;
#pragma unroll
    for (int c = 0; c < 4; c++)
        if (k0 + c < L) m = fmaxf(m, xs[c]);
#pragma unroll
    for (int s = 16; s > 0; s >>= 1)
        m = fmaxf(m, __shfl_xor_sync(0xffffffffu, m, s));
    if (lane == 0) red[wid] = m;
    __syncthreads();
    if (wid == 0) {
        float t = red[lane & 7];
#pragma unroll
        for (int s = 4; s > 0; s >>= 1)
            t = fmaxf(t, __shfl_xor_sync(0xffffffffu, t, s));
        if (lane == 0) red[0] = t;
    }
    __syncthreads();
    float rm = red[0];
    float e[4], sum = 0.f;
#pragma unroll
    for (int c = 0; c < 4; c++) {
        e[c] = (k0 + c < L) ? expf(xs[c] - rm) : 0.f;
        sum += e[c];
    }
#pragma unroll
    for (int s = 16; s > 0; s >>= 1)
        sum += __shfl_xor_sync(0xffffffffu, sum, s);
    __syncthreads();
    if (lane == 0) red[wid] = sum;
    __syncthreads();
    if (wid == 0) {
        float t = red[lane & 7];
#pragma unroll
        for (int s = 4; s > 0; s >>= 1)
            t += __shfl_xor_sync(0xffffffffu, t, s);
        if (lane == 0) red[0] = t;
    }
    __syncthreads();
    float inv = 1.f / red[0];
    float4 o = {e[0] * inv, e[1] * inv, e[2] * inv, e[3] * inv};
    *reinterpret_cast<float4*>(&S[k0]) = o;
}

// ---------------- 4) value = P @ V (batched NN, K=1024) --------------------
// Writes into g_val (= g_Q, Q is dead after scores).
__global__ __launch_bounds__(256)
void pv_kernel() {
    __shared__ __align__(16) float As[2][8 * 128];
    __shared__ __align__(16) float Bs[2][8 * 128];
    int tid = threadIdx.x, tx = tid % 16, ty = tid / 16;
    int b = blockIdx.z;
    int m0 = blockIdx.y * 128, n0 = blockIdx.x * 128;
    const float* A  = g_S + (size_t)b * TT * TT;
    const float* Bm = g_V + (size_t)b * TT * DD;
    float acc[8][8] = {};
    GEMM_NN_LOOP(A, TT, Bm, DD, TT);
    float* C = g_val + (size_t)b * TT * DD;
#pragma unroll
    for (int i = 0; i < 8; i++) {
        size_t base = (size_t)(m0 + ty * 8 + i) * DD + n0 + tx * 8;
#pragma unroll
        for (int j = 0; j < 8; j++) C[base + j] = acc[i][j];
    }
}

// ---------------- 5) conv1 (k=3 over time) + ReLU --------------------------
// GEMM with gathered A: A[row, dt*512+cin] = value[b, t+dt-1, cin] (zero pad)
// Writes g_h (= g_K, K dead after scores).
__device__ __forceinline__ float4 ldA_conv(int row, int k0, int tid) {
    int lr = tid >> 1, lc = (tid & 1) * 4;
    int r = row;                    // caller passes m0 + lr
    (void)r;
    int c = k0 + lc;
    int dt = c >> 9;                // constant across the aligned float4
    int cin = c & 511;
    int b = row >> 10;
    int t = row & 1023;
    int ts = t + dt - 1;
    if (ts >= 0 && ts < TT)
        return *reinterpret_cast<const float4*>(
            &g_val[(size_t)((b << 10) + ts) * DD + cin]);
    return make_float4(0.f, 0.f, 0.f, 0.f);
}

__global__ __launch_bounds__(256)
void conv1_kernel(const float* __restrict__ Wc1, const float* __restrict__ bc1) {
    __shared__ __align__(16) float As[2][8 * 128];
    __shared__ __align__(16) float Bs[2][8 * 128];
    int tid = threadIdx.x, tx = tid % 16, ty = tid / 16;
    int m0 = blockIdx.y * 128, n0 = blockIdx.x * 128;
    int lr = tid >> 1;
    int row = m0 + lr;
    float acc[8][8] = {};
    {
        float4 ra = ldA_conv(row, 0, tid);
        float4 rb = ldB_nn(Wc1, DD, 0, n0, tid);
        stAT(As[0], ra, tid);
        stB_nn(Bs[0], rb, tid);
        __syncthreads();
        const int KT = 1536 / 8;
        for (int kt = 0; kt < KT; kt++) {
            int cur = kt & 1;
            if (kt + 1 < KT) {
                ra = ldA_conv(row, (kt + 1) * 8, tid);
                rb = ldB_nn(Wc1, DD, (kt + 1) * 8, n0, tid);
            }
            mmac(As[cur], Bs[cur], acc, ty, tx);
            if (kt + 1 < KT) {
                stAT(As[cur ^ 1], ra, tid);
                stB_nn(Bs[cur ^ 1], rb, tid);
            }
            __syncthreads();
        }
    }
    float bb[8];
#pragma unroll
    for (int j = 0; j < 8; j++) bb[j] = bc1[n0 + tx * 8 + j];
#pragma unroll
    for (int i = 0; i < 8; i++) {
        size_t base = (size_t)(m0 + ty * 8 + i) * DD + n0 + tx * 8;
#pragma unroll
        for (int j = 0; j < 8; j++)
            g_h[base + j] = fmaxf(acc[i][j] + bb[j], 0.f);
    }
}

// ---------------- 6) conv2 (1x1) + sigmoid gate + enhanced -----------------
// Writes g_enh (= g_V, V dead after pv).
__global__ __launch_bounds__(256)
void gate_kernel(const float* __restrict__ Wc2, const float* __restrict__ bc2,
                 const float* __restrict__ aud, const int* __restrict__ vl) {
    __shared__ __align__(16) float As[2][8 * 128];
    __shared__ __align__(16) float Bs[2][8 * 128];
    int tid = threadIdx.x, tx = tid % 16, ty = tid / 16;
    int m0 = blockIdx.y * 128, n0 = blockIdx.x * 128;
    float acc[8][8] = {};
    GEMM_NN_LOOP(g_h, DD, Wc2, DD, DD);
    float bb[8];
#pragma unroll
    for (int j = 0; j < 8; j++) bb[j] = bc2[n0 + tx * 8 + j];
#pragma unroll
    for (int i = 0; i < 8; i++) {
        int row = m0 + ty * 8 + i;
        int b = row >> 10;
        int t = row & 1023;
        int L = vlen_of(vl, b);
        float valid = (t < L) ? 1.f : 0.f;
        size_t base = (size_t)row * DD + n0 + tx * 8;
#pragma unroll
        for (int j = 0; j < 8; j++) {
            float hval = acc[i][j] + bb[j];
            float g = valid / (1.f + expf(-hval));
            float a = aud[base + j];
            g_enh[base + j] = a * g + a;
        }
    }
}

// ---------------- 7) final: out = [enh | vid] @ Wf + bf --------------------
__device__ __forceinline__ float4 ldA_cat(const float* __restrict__ vid,
                                          int row, int k0, int tid) {
    int lr = tid >> 1, lc = (tid & 1) * 4;
    int c = k0 + lc;
    const float* src = (c < 512) ? &g_enh[(size_t)(row) * DD + c]
                                 : &vid[(size_t)(row) * DD + (c - 512)];
    (void)lr;
    return *reinterpret_cast<const float4*>(src);
}

__global__ __launch_bounds__(256)
void final_kernel(const float* __restrict__ vid, const float* __restrict__ Wf,
                  const float* __restrict__ bf, float* __restrict__ out) {
    __shared__ __align__(16) float As[2][8 * 128];
    __shared__ __align__(16) float Bs[2][8 * 128];
    int tid = threadIdx.x, tx = tid % 16, ty = tid / 16;
    int m0 = blockIdx.y * 128, n0 = blockIdx.x * 128;
    int lr = tid >> 1;
    int row = m0 + lr;
    float acc[8][8] = {};
    {
        float4 ra = ldA_cat(vid, row, 0, tid);
        float4 rb = ldB_nn(Wf, DD, 0, n0, tid);
        stAT(As[0], ra, tid);
        stB_nn(Bs[0], rb, tid);
        __syncthreads();
        const int KT = 1024 / 8;
        for (int kt = 0; kt < KT; kt++) {
            int cur = kt & 1;
            if (kt + 1 < KT) {
                ra = ldA_cat(vid, row, (kt + 1) * 8, tid);
                rb = ldB_nn(Wf, DD, (kt + 1) * 8, n0, tid);
            }
            mmac(As[cur], Bs[cur], acc, ty, tx);
            if (kt + 1 < KT) {
                stAT(As[cur ^ 1], ra, tid);
                stB_nn(Bs[cur ^ 1], rb, tid);
            }
            __syncthreads();
        }
    }
    float bb[8];
#pragma unroll
    for (int j = 0; j < 8; j++) bb[j] = bf[n0 + tx * 8 + j];
#pragma unroll
    for (int i = 0; i < 8; i++) {
        size_t base = (size_t)(m0 + ty * 8 + i) * DD + n0 + tx * 8;
#pragma unroll
        for (int j = 0; j < 8; j++) out[base + j] = acc[i][j] + bb[j];
    }
}

// ---------------- launch ---------------------------------------------------
extern "C" void kernel_launch(void* const* d_in, const int* in_sizes, int n_in,
                              void* d_out, int out_size) {
    const float* aud = (const float*)d_in[0];
    const float* vid = (const float*)d_in[1];
    const int*   vl  = (const int*)  d_in[2];   // int32 or int64 (detected in-kernel)
    const float* Wq  = (const float*)d_in[3];
    const float* bq  = (const float*)d_in[4];
    const float* Wk  = (const float*)d_in[5];
    const float* bk  = (const float*)d_in[6];
    const float* Wv  = (const float*)d_in[7];
    const float* bv  = (const float*)d_in[8];
    const float* Wc1 = (const float*)d_in[9];
    const float* bc1 = (const float*)d_in[10];
    const float* Wc2 = (const float*)d_in[11];
    const float* bc2 = (const float*)d_in[12];
    const float* Wf  = (const float*)d_in[13];
    const float* bf  = (const float*)d_in[14];
    float* out = (float*)d_out;

    float *dQ, *dK, *dV;
    cudaGetSymbolAddress((void**)&dQ, g_Q);
    cudaGetSymbolAddress((void**)&dK, g_K);
    cudaGetSymbolAddress((void**)&dV, g_V);

    dim3 blk(256);
    dim3 g_proj(DD / 128, MTOT / 128);       // (4, 128)
    dim3 g_sc(TT / 128, TT / 128, BB);       // (8, 8, 16)
    dim3 g_pv(DD / 128, TT / 128, BB);       // (4, 8, 16)

    proj_kernel<<<g_proj, blk>>>(aud, Wq, bq, dQ);
    proj_kernel<<<g_proj, blk>>>(vid, Wk, bk, dK);
    proj_kernel<<<g_proj, blk>>>(vid, Wv, bv, dV);
    scores_kernel<<<g_sc, blk>>>();
    softmax_kernel<<<MTOT, 256>>>(vl);
    pv_kernel<<<g_pv, blk>>>();
    conv1_kernel<<<g_proj, blk>>>(Wc1, bc1);
    gate_kernel<<<g_proj, blk>>>(Wc2, bc2, aud, vl);
    final_kernel<<<g_proj, blk>>>(vid, Wf, bf, out);
}

// round 5
// speedup vs baseline: 2.2108x; 2.2108x over previous
#include <cuda_runtime.h>
#include <cuda_bf16.h>
#include <math.h>
#include <stdint.h>

// Problem constants
#define BB 16
#define TT 1024
#define DD 512
#define MTOT (BB * TT)                  // 16384
#define SCALE 0.04419417382415922f      // 1/sqrt(512)

// =================== helpers (plain sm_80+ features only) ==================
__device__ __forceinline__ uint32_t smem_u32_of(const void* p) {
    uint32_t a;
    asm("{ .reg .u64 t; cvta.to.shared.u64 t, %1; cvt.u32.u64 %0, t; }"
        : "=r"(a) : "l"(p));
    return a;
}
__device__ __forceinline__ void cpa16(uint32_t dst, const void* src) {
    asm volatile("cp.async.cg.shared.global [%0], [%1], 16;"
                 :: "r"(dst), "l"(src));
}
__device__ __forceinline__ void cpa16z(uint32_t dst, const void* src, int sz) {
    asm volatile("cp.async.cg.shared.global [%0], [%1], 16, %2;"
                 :: "r"(dst), "l"(src), "r"(sz));
}
#define CP_COMMIT() asm volatile("cp.async.commit_group;" ::: "memory")
#define CP_WAIT0()  asm volatile("cp.async.wait_group 0;" ::: "memory")

__device__ __forceinline__ void ldm4(uint32_t r[4], uint32_t addr) {
    asm volatile("ldmatrix.sync.aligned.m8n8.x4.shared.b16 {%0,%1,%2,%3}, [%4];"
                 : "=r"(r[0]), "=r"(r[1]), "=r"(r[2]), "=r"(r[3]) : "r"(addr));
}
#define MMA_BF16(c, a, b)                                                      \
    asm volatile("mma.sync.aligned.m16n8k16.row.col.f32.bf16.bf16.f32 "        \
        "{%0,%1,%2,%3},{%4,%5,%6,%7},{%8,%9},{%0,%1,%2,%3};"                   \
        : "+f"((c)[0]), "+f"((c)[1]), "+f"((c)[2]), "+f"((c)[3])               \
        : "r"((a)[0]), "r"((a)[1]), "r"((a)[2]), "r"((a)[3]),                  \
          "r"((b)[0]), "r"((b)[1]))

__device__ __forceinline__ uint32_t sw128(uint32_t off) {
    return off ^ ((off >> 3) & 0x70);
}

// =================== scratch (bf16 split pairs, ~169 MB) ===================
__device__ __nv_bfloat16 g_Qh[MTOT * DD],   g_Ql[MTOT * DD];
__device__ __nv_bfloat16 g_Kh[MTOT * DD],   g_Kl[MTOT * DD];
__device__ __nv_bfloat16 g_Vth[MTOT * DD],  g_Vtl[MTOT * DD];   // V^T [b][d][t]
__device__ __nv_bfloat16 g_Sh[BB * TT * TT], g_Sl[BB * TT * TT]; // logits->probs
#define g_valh g_Qh
#define g_vall g_Ql
#define g_hh   g_Kh
#define g_hl   g_Kl
#define g_enhh g_Vth
#define g_enhl g_Vtl
// transposed+split weights [N, K]
__device__ __nv_bfloat16 g_Wqth[DD * DD],    g_Wqtl[DD * DD];
__device__ __nv_bfloat16 g_Wkth[DD * DD],    g_Wktl[DD * DD];
__device__ __nv_bfloat16 g_Wvth[DD * DD],    g_Wvtl[DD * DD];
__device__ __nv_bfloat16 g_Wc1th[DD * 1536], g_Wc1tl[DD * 1536];
__device__ __nv_bfloat16 g_Wc2th[DD * DD],   g_Wc2tl[DD * DD];
__device__ __nv_bfloat16 g_Wfth[DD * 1024],  g_Wftl[DD * 1024];

__device__ __forceinline__ void split2(float v, __nv_bfloat16& h, __nv_bfloat16& l) {
    h = __float2bfloat16(v);
    l = __float2bfloat16(v - __bfloat162float(h));
}
__device__ __forceinline__ void split_pack(float v0, float v1,
                                           uint32_t& hp, uint32_t& lp) {
    __nv_bfloat16 h0, l0, h1, l1;
    split2(v0, h0, l0);
    split2(v1, h1, l1);
    hp = (uint32_t)__bfloat16_as_ushort(h0) |
         ((uint32_t)__bfloat16_as_ushort(h1) << 16);
    lp = (uint32_t)__bfloat16_as_ushort(l0) |
         ((uint32_t)__bfloat16_as_ushort(l1) << 16);
}
__device__ __forceinline__ int vlen_of(const int* __restrict__ vl, int b) {
    int stride = (vl[1] == 0) ? 2 : 1;   // int64 vs int32 (values in [1,1024])
    return vl[b * stride];
}

// =================== prep: weight transpose + split ========================
__global__ __launch_bounds__(256)
void wtrans_kernel(const float* __restrict__ W, int K, int N,
                   __nv_bfloat16* __restrict__ Th, __nv_bfloat16* __restrict__ Tl) {
    __shared__ float t[32][33];
    int n0 = blockIdx.x * 32, k0 = blockIdx.y * 32;
    int tx = threadIdx.x & 31, ty = threadIdx.x >> 5;
    for (int i = ty; i < 32; i += 8)
        t[i][tx] = W[(size_t)(k0 + i) * N + n0 + tx];
    __syncthreads();
    for (int i = ty; i < 32; i += 8) {
        __nv_bfloat16 h, l;
        split2(t[tx][i], h, l);
        size_t o = (size_t)(n0 + i) * K + k0 + tx;
        Th[o] = h;
        Tl[o] = l;
    }
}

// =================== masked softmax (in place on split logits) =============
__global__ __launch_bounds__(256)
void softmax_kernel(const int* __restrict__ vl) {
    __shared__ float red[8];
    int row = blockIdx.x;
    int b = row >> 10;
    int L = vlen_of(vl, b);
    size_t rbase = (size_t)row * TT;
    int tid = threadIdx.x, lane = tid & 31, wid = tid >> 5;
    int k0 = tid * 4;
    float xs[4];
#pragma unroll
    for (int c = 0; c < 4; c++)
        xs[c] = __bfloat162float(g_Sh[rbase + k0 + c]) +
                __bfloat162float(g_Sl[rbase + k0 + c]);
    float m = -3.4e38f;
#pragma unroll
    for (int c = 0; c < 4; c++)
        if (k0 + c < L) m = fmaxf(m, xs[c]);
#pragma unroll
    for (int s = 16; s > 0; s >>= 1)
        m = fmaxf(m, __shfl_xor_sync(0xffffffffu, m, s));
    if (lane == 0) red[wid] = m;
    __syncthreads();
    if (wid == 0) {
        float t = red[lane & 7];
#pragma unroll
        for (int s = 4; s > 0; s >>= 1)
            t = fmaxf(t, __shfl_xor_sync(0xffffffffu, t, s));
        if (lane == 0) red[0] = t;
    }
    __syncthreads();
    float rm = red[0];
    float e[4], sum = 0.f;
#pragma unroll
    for (int c = 0; c < 4; c++) {
        e[c] = (k0 + c < L) ? expf(xs[c] - rm) : 0.f;
        sum += e[c];
    }
#pragma unroll
    for (int s = 16; s > 0; s >>= 1)
        sum += __shfl_xor_sync(0xffffffffu, sum, s);
    __syncthreads();
    if (lane == 0) red[wid] = sum;
    __syncthreads();
    if (wid == 0) {
        float t = red[lane & 7];
#pragma unroll
        for (int s = 4; s > 0; s >>= 1)
            t += __shfl_xor_sync(0xffffffffu, t, s);
        if (lane == 0) red[0] = t;
    }
    __syncthreads();
    float inv = 1.f / red[0];
#pragma unroll
    for (int c = 0; c < 4; c++) {
        __nv_bfloat16 h, l;
        split2(e[c] * inv, h, l);
        g_Sh[rbase + k0 + c] = h;
        g_Sl[rbase + k0 + c] = l;
    }
}

// =================== mma.sync bf16x3 GEMM ==================================
// MODE: 0=Qproj 1=Kproj 2=Vproj(T out) 3=scores 4=PV 5=conv1 6=gate 7=final
// SMEM stage: [Ah 16K][Al 16K][Bh 16K][Bl 16K] x2 = 128 KB
#define SA_H 0
#define SA_L 16384
#define SB_H 32768
#define SB_L 49152
#define STAGE_BYTES 65536

__device__ __forceinline__ void split8_sts(char* dh, char* dl, uint32_t so,
                                           const float* __restrict__ src) {
    float4 v0 = *reinterpret_cast<const float4*>(src);
    float4 v1 = *reinterpret_cast<const float4*>(src + 4);
    float xs[8] = {v0.x, v0.y, v0.z, v0.w, v1.x, v1.y, v1.z, v1.w};
    __nv_bfloat16 h[8], l[8];
#pragma unroll
    for (int c = 0; c < 8; c++) split2(xs[c], h[c], l[c]);
    *reinterpret_cast<uint4*>(dh + so) = *reinterpret_cast<uint4*>(h);
    *reinterpret_cast<uint4*>(dl + so) = *reinterpret_cast<uint4*>(l);
}

__device__ __forceinline__ void load_tileB(uint32_t sbase, int stage,
        const __nv_bfloat16* __restrict__ Bh, const __nv_bfloat16* __restrict__ Bl,
        int n0, int ldb, int kc, int tid) {
    uint32_t dh = sbase + stage * STAGE_BYTES + SB_H;
    uint32_t dl = sbase + stage * STAGE_BYTES + SB_L;
#pragma unroll
    for (int it = 0; it < 4; it++) {
        int idx = it * 256 + tid;
        int r = idx >> 3, c8 = idx & 7;
        size_t off = (size_t)(n0 + r) * ldb + kc * 64 + c8 * 8;
        uint32_t so = sw128((uint32_t)(r * 128 + c8 * 16));
        cpa16(dh + so, Bh + off);
        cpa16(dl + so, Bl + off);
    }
}

template <int MODE>
__device__ __forceinline__ void load_tileA(char* smem, uint32_t sbase, int stage,
        const __nv_bfloat16* __restrict__ Ah, const __nv_bfloat16* __restrict__ Al,
        const float* __restrict__ xin, int m0, int lda, int kc, int tid) {
    uint32_t dhu = sbase + stage * STAGE_BYTES + SA_H;
    uint32_t dlu = sbase + stage * STAGE_BYTES + SA_L;
    char* dhc = smem + stage * STAGE_BYTES + SA_H;
    char* dlc = smem + stage * STAGE_BYTES + SA_L;
#pragma unroll
    for (int it = 0; it < 4; it++) {
        int idx = it * 256 + tid;
        int r = idx >> 3, c8 = idx & 7;
        uint32_t so = sw128((uint32_t)(r * 128 + c8 * 16));
        if constexpr (MODE <= 2) {
            split8_sts(dhc, dlc, so, &xin[(size_t)(m0 + r) * DD + kc * 64 + c8 * 8]);
        } else if constexpr (MODE == 5) {
            int gr = m0 + r, b = gr >> 10, t = gr & 1023;
            int ts = t + (kc >> 3) - 1;
            int ok = ((unsigned)ts < (unsigned)TT) ? 16 : 0;
            int tsc = min(max(ts, 0), TT - 1);
            size_t off = (size_t)((b << 10) + tsc) * DD + (kc & 7) * 64 + c8 * 8;
            cpa16z(dhu + so, g_valh + off, ok);
            cpa16z(dlu + so, g_vall + off, ok);
        } else if constexpr (MODE == 7) {
            int gr = m0 + r;
            if (kc < 8) {
                size_t off = (size_t)gr * DD + kc * 64 + c8 * 8;
                cpa16(dhu + so, g_enhh + off);
                cpa16(dlu + so, g_enhl + off);
            } else {
                split8_sts(dhc, dlc, so,
                           &xin[(size_t)gr * DD + (kc - 8) * 64 + c8 * 8]);
            }
        } else {
            size_t off = (size_t)(m0 + r) * lda + kc * 64 + c8 * 8;
            cpa16(dhu + so, Ah + off);
            cpa16(dlu + so, Al + off);
        }
    }
}

template <int MODE>
__global__ __launch_bounds__(256)
void gemm_kernel(const float* __restrict__ bias, const float* __restrict__ xin,
                 const int* __restrict__ vlen, float* __restrict__ fout) {
    constexpr int KTOT = (MODE == 5) ? 1536 : ((MODE == 4 || MODE == 7) ? 1024 : 512);
    constexpr int KT = KTOT / 64;

    extern __shared__ char smem[];
    int tid = threadIdx.x, wid = tid >> 5, lane = tid & 31;
    int bx = blockIdx.x, by = blockIdx.y, bz = blockIdx.z;
    uint32_t sbase = smem_u32_of(smem);
    int m0 = by * 128, n0 = bx * 128;

    const __nv_bfloat16 *Ah = nullptr, *Al = nullptr, *Bh = nullptr, *Bl = nullptr;
    int lda = 512, ldb = 512;
    if constexpr (MODE == 0) { Bh = g_Wqth; Bl = g_Wqtl; }
    if constexpr (MODE == 1) { Bh = g_Wkth; Bl = g_Wktl; }
    if constexpr (MODE == 2) { Bh = g_Wvth; Bl = g_Wvtl; }
    if constexpr (MODE == 3) {
        size_t bo = (size_t)bz * TT * DD;
        Ah = g_Qh + bo; Al = g_Ql + bo; Bh = g_Kh + bo; Bl = g_Kl + bo;
    }
    if constexpr (MODE == 4) {
        Ah = g_Sh + (size_t)bz * TT * TT; Al = g_Sl + (size_t)bz * TT * TT; lda = 1024;
        Bh = g_Vth + (size_t)bz * DD * TT; Bl = g_Vtl + (size_t)bz * DD * TT; ldb = 1024;
    }
    if constexpr (MODE == 5) { Bh = g_Wc1th; Bl = g_Wc1tl; ldb = 1536; }
    if constexpr (MODE == 6) { Ah = g_hh; Al = g_hl; Bh = g_Wc2th; Bl = g_Wc2tl; }
    if constexpr (MODE == 7) { Bh = g_Wfth; Bl = g_Wftl; ldb = 1024; }

    float acc[4][4][4];
#pragma unroll
    for (int i = 0; i < 4; i++)
#pragma unroll
        for (int j = 0; j < 4; j++)
#pragma unroll
            for (int c = 0; c < 4; c++) acc[i][j][c] = 0.f;

    // prologue: chunk 0 -> stage 0
    load_tileA<MODE>(smem, sbase, 0, Ah, Al, xin, m0, lda, 0, tid);
    load_tileB(sbase, 0, Bh, Bl, n0, ldb, 0, tid);
    CP_COMMIT();

    int wm = (wid & 1) * 64, wn = (wid >> 1) * 32;
    // ldmatrix per-lane address components
    int a_r = (lane & 7) + ((lane >> 3) & 1) * 8;
    int a_c = ((lane >> 4) & 1) * 16;
    int b_r = (lane & 7) + ((lane >> 4) & 1) * 8;
    int b_c = ((lane >> 3) & 1) * 16;

    for (int kt = 0; kt < KT; kt++) {
        int cur = kt & 1;
        CP_WAIT0();
        __syncthreads();
        if (kt + 1 < KT) {
            load_tileA<MODE>(smem, sbase, cur ^ 1, Ah, Al, xin, m0, lda, kt + 1, tid);
            load_tileB(sbase, cur ^ 1, Bh, Bl, n0, ldb, kt + 1, tid);
            CP_COMMIT();
        }
        uint32_t bufb = sbase + cur * STAGE_BYTES;
#pragma unroll
        for (int ks = 0; ks < 4; ks++) {
            int kb = ks * 32;
            uint32_t ahf[4][4], alf[4][4], bhf[4][2], blf[4][2];
#pragma unroll
            for (int i = 0; i < 4; i++) {
                uint32_t so = sw128((uint32_t)((wm + i * 16 + a_r) * 128 + kb + a_c));
                ldm4(ahf[i], bufb + SA_H + so);
                ldm4(alf[i], bufb + SA_L + so);
            }
#pragma unroll
            for (int j = 0; j < 2; j++) {
                uint32_t so = sw128((uint32_t)((wn + j * 16 + b_r) * 128 + kb + b_c));
                uint32_t t[4];
                ldm4(t, bufb + SB_H + so);
                bhf[2 * j][0] = t[0]; bhf[2 * j][1] = t[1];
                bhf[2 * j + 1][0] = t[2]; bhf[2 * j + 1][1] = t[3];
                ldm4(t, bufb + SB_L + so);
                blf[2 * j][0] = t[0]; blf[2 * j][1] = t[1];
                blf[2 * j + 1][0] = t[2]; blf[2 * j + 1][1] = t[3];
            }
#pragma unroll
            for (int i = 0; i < 4; i++)
#pragma unroll
                for (int j = 0; j < 4; j++) {
                    MMA_BF16(acc[i][j], ahf[i], bhf[j]);
                    MMA_BF16(acc[i][j], ahf[i], blf[j]);
                    MMA_BF16(acc[i][j], alf[i], bhf[j]);
                }
        }
    }

    // ---------------- epilogue ----------------
    if constexpr (MODE == 2) {
        __syncthreads();                       // smem buffers now reusable
        float* s = reinterpret_cast<float*>(smem);
#pragma unroll
        for (int i = 0; i < 4; i++)
#pragma unroll
            for (int j = 0; j < 4; j++) {
                int r0 = wm + i * 16 + (lane >> 2);
                int c = wn + j * 8 + 2 * (lane & 3);
                s[r0 * 130 + c]       = acc[i][j][0] + bias[n0 + c];
                s[r0 * 130 + c + 1]   = acc[i][j][1] + bias[n0 + c + 1];
                s[(r0 + 8) * 130 + c]     = acc[i][j][2] + bias[n0 + c];
                s[(r0 + 8) * 130 + c + 1] = acc[i][j][3] + bias[n0 + c + 1];
            }
        __syncthreads();
        int d = tid >> 1, half = (tid & 1) * 64;
        int b = m0 >> 10, t0 = (m0 & 1023) + half;
        size_t obase = ((size_t)b * DD + n0 + d) * TT + t0;
        for (int m = 0; m < 64; m++) {
            __nv_bfloat16 h, l;
            split2(s[(half + m) * 130 + d], h, l);
            g_Vth[obase + m] = h;
            g_Vtl[obase + m] = l;
        }
    } else {
#pragma unroll
        for (int i = 0; i < 4; i++)
#pragma unroll
            for (int j = 0; j < 4; j++) {
#pragma unroll
                for (int half = 0; half < 2; half++) {
                    int grow = m0 + wm + i * 16 + (lane >> 2) + half * 8;
                    int gcol = n0 + wn + j * 8 + 2 * (lane & 3);
                    float v0 = acc[i][j][half * 2];
                    float v1 = acc[i][j][half * 2 + 1];
                    if constexpr (MODE == 0 || MODE == 1) {
                        v0 += bias[gcol]; v1 += bias[gcol + 1];
                        uint32_t hp, lp;
                        split_pack(v0, v1, hp, lp);
                        size_t o = (size_t)grow * DD + gcol;
                        if constexpr (MODE == 0) {
                            *reinterpret_cast<uint32_t*>(&g_Qh[o]) = hp;
                            *reinterpret_cast<uint32_t*>(&g_Ql[o]) = lp;
                        } else {
                            *reinterpret_cast<uint32_t*>(&g_Kh[o]) = hp;
                            *reinterpret_cast<uint32_t*>(&g_Kl[o]) = lp;
                        }
                    } else if constexpr (MODE == 3) {
                        uint32_t hp, lp;
                        split_pack(v0 * SCALE, v1 * SCALE, hp, lp);
                        size_t o = ((size_t)bz * TT + grow) * TT + gcol;
                        *reinterpret_cast<uint32_t*>(&g_Sh[o]) = hp;
                        *reinterpret_cast<uint32_t*>(&g_Sl[o]) = lp;
                    } else if constexpr (MODE == 4) {
                        uint32_t hp, lp;
                        split_pack(v0, v1, hp, lp);
                        size_t o = ((size_t)bz * TT + grow) * DD + gcol;
                        *reinterpret_cast<uint32_t*>(&g_valh[o]) = hp;
                        *reinterpret_cast<uint32_t*>(&g_vall[o]) = lp;
                    } else if constexpr (MODE == 5) {
                        v0 = fmaxf(v0 + bias[gcol], 0.f);
                        v1 = fmaxf(v1 + bias[gcol + 1], 0.f);
                        uint32_t hp, lp;
                        split_pack(v0, v1, hp, lp);
                        size_t o = (size_t)grow * DD + gcol;
                        *reinterpret_cast<uint32_t*>(&g_hh[o]) = hp;
                        *reinterpret_cast<uint32_t*>(&g_hl[o]) = lp;
                    } else if constexpr (MODE == 6) {
                        int b = grow >> 10, t = grow & 1023;
                        int L = vlen_of(vlen, b);
                        float valid = (t < L) ? 1.f : 0.f;
                        size_t o = (size_t)grow * DD + gcol;
                        float2 a2 = *reinterpret_cast<const float2*>(&xin[o]);
                        float g0 = valid / (1.f + expf(-(v0 + bias[gcol])));
                        float g1 = valid / (1.f + expf(-(v1 + bias[gcol + 1])));
                        uint32_t hp, lp;
                        split_pack(a2.x * g0 + a2.x, a2.y * g1 + a2.y, hp, lp);
                        *reinterpret_cast<uint32_t*>(&g_enhh[o]) = hp;
                        *reinterpret_cast<uint32_t*>(&g_enhl[o]) = lp;
                    } else {  // MODE 7
                        size_t o = (size_t)grow * DD + gcol;
                        float2 r2 = {v0 + bias[gcol], v1 + bias[gcol + 1]};
                        *reinterpret_cast<float2*>(&fout[o]) = r2;
                    }
                }
            }
    }
}

// =================== launch ================================================
extern "C" void kernel_launch(void* const* d_in, const int* in_sizes, int n_in,
                              void* d_out, int out_size) {
    const float* aud = (const float*)d_in[0];
    const float* vid = (const float*)d_in[1];
    const int*   vl  = (const int*)  d_in[2];
    const float* Wq  = (const float*)d_in[3];
    const float* bq  = (const float*)d_in[4];
    const float* Wk  = (const float*)d_in[5];
    const float* bk  = (const float*)d_in[6];
    const float* Wv  = (const float*)d_in[7];
    const float* bv  = (const float*)d_in[8];
    const float* Wc1 = (const float*)d_in[9];
    const float* bc1 = (const float*)d_in[10];
    const float* Wc2 = (const float*)d_in[11];
    const float* bc2 = (const float*)d_in[12];
    const float* Wf  = (const float*)d_in[13];
    const float* bf  = (const float*)d_in[14];
    float* out = (float*)d_out;

    cudaFuncSetAttribute(gemm_kernel<0>, cudaFuncAttributeMaxDynamicSharedMemorySize, 131072);
    cudaFuncSetAttribute(gemm_kernel<1>, cudaFuncAttributeMaxDynamicSharedMemorySize, 131072);
    cudaFuncSetAttribute(gemm_kernel<2>, cudaFuncAttributeMaxDynamicSharedMemorySize, 131072);
    cudaFuncSetAttribute(gemm_kernel<3>, cudaFuncAttributeMaxDynamicSharedMemorySize, 131072);
    cudaFuncSetAttribute(gemm_kernel<4>, cudaFuncAttributeMaxDynamicSharedMemorySize, 131072);
    cudaFuncSetAttribute(gemm_kernel<5>, cudaFuncAttributeMaxDynamicSharedMemorySize, 131072);
    cudaFuncSetAttribute(gemm_kernel<6>, cudaFuncAttributeMaxDynamicSharedMemorySize, 131072);
    cudaFuncSetAttribute(gemm_kernel<7>, cudaFuncAttributeMaxDynamicSharedMemorySize, 131072);

    __nv_bfloat16 *wqh, *wql, *wkh, *wkl, *wvh, *wvl, *w1h, *w1l, *w2h, *w2l, *wfh, *wfl;
    cudaGetSymbolAddress((void**)&wqh, g_Wqth);
    cudaGetSymbolAddress((void**)&wql, g_Wqtl);
    cudaGetSymbolAddress((void**)&wkh, g_Wkth);
    cudaGetSymbolAddress((void**)&wkl, g_Wktl);
    cudaGetSymbolAddress((void**)&wvh, g_Wvth);
    cudaGetSymbolAddress((void**)&wvl, g_Wvtl);
    cudaGetSymbolAddress((void**)&w1h, g_Wc1th);
    cudaGetSymbolAddress((void**)&w1l, g_Wc1tl);
    cudaGetSymbolAddress((void**)&w2h, g_Wc2th);
    cudaGetSymbolAddress((void**)&w2l, g_Wc2tl);
    cudaGetSymbolAddress((void**)&wfh, g_Wfth);
    cudaGetSymbolAddress((void**)&wfl, g_Wftl);

    wtrans_kernel<<<dim3(16, 16), 256>>>(Wq, 512, 512, wqh, wql);
    wtrans_kernel<<<dim3(16, 16), 256>>>(Wk, 512, 512, wkh, wkl);
    wtrans_kernel<<<dim3(16, 16), 256>>>(Wv, 512, 512, wvh, wvl);
    wtrans_kernel<<<dim3(16, 48), 256>>>(Wc1, 1536, 512, w1h, w1l);
    wtrans_kernel<<<dim3(16, 16), 256>>>(Wc2, 512, 512, w2h, w2l);
    wtrans_kernel<<<dim3(16, 32), 256>>>(Wf, 1024, 512, wfh, wfl);

    const size_t SM = 131072;
    gemm_kernel<0><<<dim3(4, 128), 256, SM>>>(bq, aud, vl, nullptr);
    gemm_kernel<1><<<dim3(4, 128), 256, SM>>>(bk, vid, vl, nullptr);
    gemm_kernel<2><<<dim3(4, 128), 256, SM>>>(bv, vid, vl, nullptr);
    gemm_kernel<3><<<dim3(8, 8, 16), 256, SM>>>(nullptr, nullptr, vl, nullptr);
    softmax_kernel<<<MTOT, 256>>>(vl);
    gemm_kernel<4><<<dim3(4, 8, 16), 256, SM>>>(nullptr, nullptr, vl, nullptr);
    gemm_kernel<5><<<dim3(4, 128), 256, SM>>>(bc1, nullptr, vl, nullptr);
    gemm_kernel<6><<<dim3(4, 128), 256, SM>>>(bc2, aud, vl, nullptr);
    gemm_kernel<7><<<dim3(4, 128), 256, SM>>>(bf, vid, vl, out);
}

// round 6
// speedup vs baseline: 2.5943x; 1.1735x over previous
#include <cuda_runtime.h>
#include <cuda_bf16.h>
#include <math.h>
#include <stdint.h>

// Problem constants
#define BB 16
#define TT 1024
#define DD 512
#define MTOT (BB * TT)                  // 16384
#define SCALE 0.04419417382415922f      // 1/sqrt(512)

// =================== helpers (plain sm_80+ features only) ==================
__device__ __forceinline__ uint32_t smem_u32_of(const void* p) {
    uint32_t a;
    asm("{ .reg .u64 t; cvta.to.shared.u64 t, %1; cvt.u32.u64 %0, t; }"
        : "=r"(a) : "l"(p));
    return a;
}
__device__ __forceinline__ void cpa16(uint32_t dst, const void* src) {
    asm volatile("cp.async.cg.shared.global [%0], [%1], 16;"
                 :: "r"(dst), "l"(src));
}
__device__ __forceinline__ void cpa16z(uint32_t dst, const void* src, int sz) {
    asm volatile("cp.async.cg.shared.global [%0], [%1], 16, %2;"
                 :: "r"(dst), "l"(src), "r"(sz));
}
#define CP_COMMIT() asm volatile("cp.async.commit_group;" ::: "memory")
#define CP_WAIT0()  asm volatile("cp.async.wait_group 0;" ::: "memory")

__device__ __forceinline__ void ldm4(uint32_t r[4], uint32_t addr) {
    asm volatile("ldmatrix.sync.aligned.m8n8.x4.shared.b16 {%0,%1,%2,%3}, [%4];"
                 : "=r"(r[0]), "=r"(r[1]), "=r"(r[2]), "=r"(r[3]) : "r"(addr));
}
#define MMA_BF16(c, a, b0, b1)                                                 \
    asm volatile("mma.sync.aligned.m16n8k16.row.col.f32.bf16.bf16.f32 "        \
        "{%0,%1,%2,%3},{%4,%5,%6,%7},{%8,%9},{%0,%1,%2,%3};"                   \
        : "+f"((c)[0]), "+f"((c)[1]), "+f"((c)[2]), "+f"((c)[3])               \
        : "r"((a)[0]), "r"((a)[1]), "r"((a)[2]), "r"((a)[3]),                  \
          "r"(b0), "r"(b1))

__device__ __forceinline__ uint32_t sw128(uint32_t off) {
    return off ^ ((off >> 3) & 0x70);
}

// =================== scratch (bf16 split pairs, ~169 MB) ===================
__device__ __nv_bfloat16 g_Qh[MTOT * DD],   g_Ql[MTOT * DD];
__device__ __nv_bfloat16 g_Kh[MTOT * DD],   g_Kl[MTOT * DD];
__device__ __nv_bfloat16 g_Vth[MTOT * DD],  g_Vtl[MTOT * DD];   // V^T [b][d][t]
__device__ __nv_bfloat16 g_Sh[BB * TT * TT], g_Sl[BB * TT * TT]; // logits->probs
#define g_valh g_Qh
#define g_vall g_Ql
#define g_hh   g_Kh
#define g_hl   g_Kl
#define g_enhh g_Vth
#define g_enhl g_Vtl
// transposed+split weights [N, K]
__device__ __nv_bfloat16 g_Wqth[DD * DD],    g_Wqtl[DD * DD];
__device__ __nv_bfloat16 g_Wkth[DD * DD],    g_Wktl[DD * DD];
__device__ __nv_bfloat16 g_Wvth[DD * DD],    g_Wvtl[DD * DD];
__device__ __nv_bfloat16 g_Wc1th[DD * 1536], g_Wc1tl[DD * 1536];
__device__ __nv_bfloat16 g_Wc2th[DD * DD],   g_Wc2tl[DD * DD];
__device__ __nv_bfloat16 g_Wfth[DD * 1024],  g_Wftl[DD * 1024];

__device__ __forceinline__ void split2(float v, __nv_bfloat16& h, __nv_bfloat16& l) {
    h = __float2bfloat16(v);
    l = __float2bfloat16(v - __bfloat162float(h));
}
__device__ __forceinline__ void split_pack(float v0, float v1,
                                           uint32_t& hp, uint32_t& lp) {
    __nv_bfloat16 h0, l0, h1, l1;
    split2(v0, h0, l0);
    split2(v1, h1, l1);
    hp = (uint32_t)__bfloat16_as_ushort(h0) |
         ((uint32_t)__bfloat16_as_ushort(h1) << 16);
    lp = (uint32_t)__bfloat16_as_ushort(l0) |
         ((uint32_t)__bfloat16_as_ushort(l1) << 16);
}
__device__ __forceinline__ int vlen_of(const int* __restrict__ vl, int b) {
    int stride = (vl[1] == 0) ? 2 : 1;   // int64 vs int32 (values in [1,1024])
    return vl[b * stride];
}

// =================== prep: weight transpose + split ========================
__global__ __launch_bounds__(256)
void wtrans_kernel(const float* __restrict__ W, int K, int N,
                   __nv_bfloat16* __restrict__ Th, __nv_bfloat16* __restrict__ Tl) {
    __shared__ float t[32][33];
    int n0 = blockIdx.x * 32, k0 = blockIdx.y * 32;
    int tx = threadIdx.x & 31, ty = threadIdx.x >> 5;
    for (int i = ty; i < 32; i += 8)
        t[i][tx] = W[(size_t)(k0 + i) * N + n0 + tx];
    __syncthreads();
    for (int i = ty; i < 32; i += 8) {
        __nv_bfloat16 h, l;
        split2(t[tx][i], h, l);
        size_t o = (size_t)(n0 + i) * K + k0 + tx;
        Th[o] = h;
        Tl[o] = l;
    }
}

// =================== masked softmax (in place on split logits) =============
__global__ __launch_bounds__(256)
void softmax_kernel(const int* __restrict__ vl) {
    __shared__ float red[8];
    int row = blockIdx.x;
    int b = row >> 10;
    int L = vlen_of(vl, b);
    size_t rbase = (size_t)row * TT;
    int tid = threadIdx.x, lane = tid & 31, wid = tid >> 5;
    int k0 = tid * 4;
    float xs[4];
#pragma unroll
    for (int c = 0; c < 4; c++)
        xs[c] = __bfloat162float(g_Sh[rbase + k0 + c]) +
                __bfloat162float(g_Sl[rbase + k0 + c]);
    float m = -3.4e38f;
#pragma unroll
    for (int c = 0; c < 4; c++)
        if (k0 + c < L) m = fmaxf(m, xs[c]);
#pragma unroll
    for (int s = 16; s > 0; s >>= 1)
        m = fmaxf(m, __shfl_xor_sync(0xffffffffu, m, s));
    if (lane == 0) red[wid] = m;
    __syncthreads();
    if (wid == 0) {
        float t = red[lane & 7];
#pragma unroll
        for (int s = 4; s > 0; s >>= 1)
            t = fmaxf(t, __shfl_xor_sync(0xffffffffu, t, s));
        if (lane == 0) red[0] = t;
    }
    __syncthreads();
    float rm = red[0];
    float e[4], sum = 0.f;
#pragma unroll
    for (int c = 0; c < 4; c++) {
        e[c] = (k0 + c < L) ? expf(xs[c] - rm) : 0.f;
        sum += e[c];
    }
#pragma unroll
    for (int s = 16; s > 0; s >>= 1)
        sum += __shfl_xor_sync(0xffffffffu, sum, s);
    __syncthreads();
    if (lane == 0) red[wid] = sum;
    __syncthreads();
    if (wid == 0) {
        float t = red[lane & 7];
#pragma unroll
        for (int s = 4; s > 0; s >>= 1)
            t += __shfl_xor_sync(0xffffffffu, t, s);
        if (lane == 0) red[0] = t;
    }
    __syncthreads();
    float inv = 1.f / red[0];
#pragma unroll
    for (int c = 0; c < 4; c++) {
        __nv_bfloat16 h, l;
        split2(e[c] * inv, h, l);
        g_Sh[rbase + k0 + c] = h;
        g_Sl[rbase + k0 + c] = l;
    }
}

// =================== mma.sync bf16x3 GEMM, 128x256 tiles ===================
// MODE: 0=Qproj 1=Kproj 2=Vproj(T out) 3=scores 4=PV 5=conv1 6=gate 7=final
// SMEM stage: [Ah 16K][Al 16K][Bh 32K][Bl 32K] x2 = 192 KB
#define SA_H 0
#define SA_L 16384
#define SB_H 32768
#define SB_L 65536
#define STAGE_BYTES 98304

__device__ __forceinline__ void split8_sts(char* dh, char* dl, uint32_t so,
                                           const float* __restrict__ src) {
    float4 v0 = *reinterpret_cast<const float4*>(src);
    float4 v1 = *reinterpret_cast<const float4*>(src + 4);
    float xs[8] = {v0.x, v0.y, v0.z, v0.w, v1.x, v1.y, v1.z, v1.w};
    __nv_bfloat16 h[8], l[8];
#pragma unroll
    for (int c = 0; c < 8; c++) split2(xs[c], h[c], l[c]);
    *reinterpret_cast<uint4*>(dh + so) = *reinterpret_cast<uint4*>(h);
    *reinterpret_cast<uint4*>(dl + so) = *reinterpret_cast<uint4*>(l);
}

__device__ __forceinline__ void load_tileB(uint32_t sbase, int stage,
        const __nv_bfloat16* __restrict__ Bh, const __nv_bfloat16* __restrict__ Bl,
        int n0, int ldb, int kc, int tid) {
    uint32_t dh = sbase + stage * STAGE_BYTES + SB_H;
    uint32_t dl = sbase + stage * STAGE_BYTES + SB_L;
#pragma unroll
    for (int it = 0; it < 8; it++) {               // 256 rows x 8 float4-cols
        int idx = it * 256 + tid;
        int r = idx >> 3, c8 = idx & 7;
        size_t off = (size_t)(n0 + r) * ldb + kc * 64 + c8 * 8;
        uint32_t so = sw128((uint32_t)(r * 128 + c8 * 16));
        cpa16(dh + so, Bh + off);
        cpa16(dl + so, Bl + off);
    }
}

template <int MODE>
__device__ __forceinline__ void load_tileA(char* smem, uint32_t sbase, int stage,
        const __nv_bfloat16* __restrict__ Ah, const __nv_bfloat16* __restrict__ Al,
        const float* __restrict__ xin, int m0, int lda, int kc, int tid) {
    uint32_t dhu = sbase + stage * STAGE_BYTES + SA_H;
    uint32_t dlu = sbase + stage * STAGE_BYTES + SA_L;
    char* dhc = smem + stage * STAGE_BYTES + SA_H;
    char* dlc = smem + stage * STAGE_BYTES + SA_L;
#pragma unroll
    for (int it = 0; it < 4; it++) {               // 128 rows x 8 float4-cols
        int idx = it * 256 + tid;
        int r = idx >> 3, c8 = idx & 7;
        uint32_t so = sw128((uint32_t)(r * 128 + c8 * 16));
        if constexpr (MODE <= 2) {
            split8_sts(dhc, dlc, so, &xin[(size_t)(m0 + r) * DD + kc * 64 + c8 * 8]);
        } else if constexpr (MODE == 5) {
            int gr = m0 + r, b = gr >> 10, t = gr & 1023;
            int ts = t + (kc >> 3) - 1;
            int ok = ((unsigned)ts < (unsigned)TT) ? 16 : 0;
            int tsc = min(max(ts, 0), TT - 1);
            size_t off = (size_t)((b << 10) + tsc) * DD + (kc & 7) * 64 + c8 * 8;
            cpa16z(dhu + so, g_valh + off, ok);
            cpa16z(dlu + so, g_vall + off, ok);
        } else if constexpr (MODE == 7) {
            int gr = m0 + r;
            if (kc < 8) {
                size_t off = (size_t)gr * DD + kc * 64 + c8 * 8;
                cpa16(dhu + so, g_enhh + off);
                cpa16(dlu + so, g_enhl + off);
            } else {
                split8_sts(dhc, dlc, so,
                           &xin[(size_t)gr * DD + (kc - 8) * 64 + c8 * 8]);
            }
        } else {
            size_t off = (size_t)(m0 + r) * lda + kc * 64 + c8 * 8;
            cpa16(dhu + so, Ah + off);
            cpa16(dlu + so, Al + off);
        }
    }
}

template <int MODE>
__global__ __launch_bounds__(256)
void gemm_kernel(const float* __restrict__ bias, const float* __restrict__ xin,
                 const int* __restrict__ vlen, float* __restrict__ fout) {
    constexpr int KTOT = (MODE == 5) ? 1536 : ((MODE == 4 || MODE == 7) ? 1024 : 512);
    constexpr int KT = KTOT / 64;

    extern __shared__ char smem[];
    int tid = threadIdx.x, wid = tid >> 5, lane = tid & 31;
    int bx = blockIdx.x, by = blockIdx.y, bz = blockIdx.z;
    uint32_t sbase = smem_u32_of(smem);
    int m0 = by * 128, n0 = bx * 256;

    const __nv_bfloat16 *Ah = nullptr, *Al = nullptr, *Bh = nullptr, *Bl = nullptr;
    int lda = 512, ldb = 512;
    if constexpr (MODE == 0) { Bh = g_Wqth; Bl = g_Wqtl; }
    if constexpr (MODE == 1) { Bh = g_Wkth; Bl = g_Wktl; }
    if constexpr (MODE == 2) { Bh = g_Wvth; Bl = g_Wvtl; }
    if constexpr (MODE == 3) {
        size_t bo = (size_t)bz * TT * DD;
        Ah = g_Qh + bo; Al = g_Ql + bo; Bh = g_Kh + bo; Bl = g_Kl + bo;
    }
    if constexpr (MODE == 4) {
        Ah = g_Sh + (size_t)bz * TT * TT; Al = g_Sl + (size_t)bz * TT * TT; lda = 1024;
        Bh = g_Vth + (size_t)bz * DD * TT; Bl = g_Vtl + (size_t)bz * DD * TT; ldb = 1024;
    }
    if constexpr (MODE == 5) { Bh = g_Wc1th; Bl = g_Wc1tl; ldb = 1536; }
    if constexpr (MODE == 6) { Ah = g_hh; Al = g_hl; Bh = g_Wc2th; Bl = g_Wc2tl; }
    if constexpr (MODE == 7) { Bh = g_Wfth; Bl = g_Wftl; ldb = 1024; }

    // warp tile 64x64: wm in {0,64}, wn in {0,64,128,192}
    int wm = (wid & 1) * 64, wn = (wid >> 1) * 64;
    float acc[4][8][4];
#pragma unroll
    for (int i = 0; i < 4; i++)
#pragma unroll
        for (int j = 0; j < 8; j++)
#pragma unroll
            for (int c = 0; c < 4; c++) acc[i][j][c] = 0.f;

    load_tileA<MODE>(smem, sbase, 0, Ah, Al, xin, m0, lda, 0, tid);
    load_tileB(sbase, 0, Bh, Bl, n0, ldb, 0, tid);
    CP_COMMIT();

    int a_r = (lane & 7) + ((lane >> 3) & 1) * 8;
    int a_c = ((lane >> 4) & 1) * 16;
    int b_r = (lane & 7) + ((lane >> 4) & 1) * 8;
    int b_c = ((lane >> 3) & 1) * 16;

    for (int kt = 0; kt < KT; kt++) {
        int cur = kt & 1;
        CP_WAIT0();
        __syncthreads();
        if (kt + 1 < KT) {
            load_tileA<MODE>(smem, sbase, cur ^ 1, Ah, Al, xin, m0, lda, kt + 1, tid);
            load_tileB(sbase, cur ^ 1, Bh, Bl, n0, ldb, kt + 1, tid);
            CP_COMMIT();
        }
        uint32_t bufb = sbase + cur * STAGE_BYTES;
#pragma unroll
        for (int ks = 0; ks < 4; ks++) {
            int kb = ks * 32;
            uint32_t ahf[4][4], alf[4][4];
#pragma unroll
            for (int i = 0; i < 4; i++) {
                uint32_t so = sw128((uint32_t)((wm + i * 16 + a_r) * 128 + kb + a_c));
                ldm4(ahf[i], bufb + SA_H + so);
                ldm4(alf[i], bufb + SA_L + so);
            }
#pragma unroll
            for (int j2 = 0; j2 < 4; j2++) {
                uint32_t so = sw128((uint32_t)((wn + j2 * 16 + b_r) * 128 + kb + b_c));
                uint32_t tb[4], tl[4];
                ldm4(tb, bufb + SB_H + so);
                ldm4(tl, bufb + SB_L + so);
#pragma unroll
                for (int i = 0; i < 4; i++) {
                    MMA_BF16(acc[i][2 * j2],     ahf[i], tb[0], tb[1]);
                    MMA_BF16(acc[i][2 * j2],     ahf[i], tl[0], tl[1]);
                    MMA_BF16(acc[i][2 * j2],     alf[i], tb[0], tb[1]);
                    MMA_BF16(acc[i][2 * j2 + 1], ahf[i], tb[2], tb[3]);
                    MMA_BF16(acc[i][2 * j2 + 1], ahf[i], tl[2], tl[3]);
                    MMA_BF16(acc[i][2 * j2 + 1], alf[i], tb[2], tb[3]);
                }
            }
        }
    }

    // ---------------- epilogue ----------------
    if constexpr (MODE == 2) {
        __syncthreads();
        float* s = reinterpret_cast<float*>(smem);   // 128 x 264 fp32
#pragma unroll
        for (int i = 0; i < 4; i++)
#pragma unroll
            for (int j = 0; j < 8; j++) {
                int r0 = wm + i * 16 + (lane >> 2);
                int c = wn + j * 8 + 2 * (lane & 3);
                s[r0 * 264 + c]           = acc[i][j][0] + bias[n0 + c];
                s[r0 * 264 + c + 1]       = acc[i][j][1] + bias[n0 + c + 1];
                s[(r0 + 8) * 264 + c]     = acc[i][j][2] + bias[n0 + c];
                s[(r0 + 8) * 264 + c + 1] = acc[i][j][3] + bias[n0 + c + 1];
            }
        __syncthreads();
        int d = tid;                      // 256 head-dims
        int b = m0 >> 10, t0 = m0 & 1023;
        size_t obase = ((size_t)b * DD + n0 + d) * TT + t0;
        for (int m = 0; m < 128; m += 8) {
            __nv_bfloat16 hb[8], lb[8];
#pragma unroll
            for (int q = 0; q < 8; q++)
                split2(s[(m + q) * 264 + d], hb[q], lb[q]);
            *reinterpret_cast<uint4*>(&g_Vth[obase + m]) =
                *reinterpret_cast<uint4*>(hb);
            *reinterpret_cast<uint4*>(&g_Vtl[obase + m]) =
                *reinterpret_cast<uint4*>(lb);
        }
    } else {
#pragma unroll
        for (int i = 0; i < 4; i++)
#pragma unroll
            for (int j = 0; j < 8; j++) {
#pragma unroll
                for (int half = 0; half < 2; half++) {
                    int grow = m0 + wm + i * 16 + (lane >> 2) + half * 8;
                    int gcol = n0 + wn + j * 8 + 2 * (lane & 3);
                    float v0 = acc[i][j][half * 2];
                    float v1 = acc[i][j][half * 2 + 1];
                    if constexpr (MODE == 0 || MODE == 1) {
                        v0 += bias[gcol]; v1 += bias[gcol + 1];
                        uint32_t hp, lp;
                        split_pack(v0, v1, hp, lp);
                        size_t o = (size_t)grow * DD + gcol;
                        if constexpr (MODE == 0) {
                            *reinterpret_cast<uint32_t*>(&g_Qh[o]) = hp;
                            *reinterpret_cast<uint32_t*>(&g_Ql[o]) = lp;
                        } else {
                            *reinterpret_cast<uint32_t*>(&g_Kh[o]) = hp;
                            *reinterpret_cast<uint32_t*>(&g_Kl[o]) = lp;
                        }
                    } else if constexpr (MODE == 3) {
                        uint32_t hp, lp;
                        split_pack(v0 * SCALE, v1 * SCALE, hp, lp);
                        size_t o = ((size_t)bz * TT + grow) * TT + gcol;
                        *reinterpret_cast<uint32_t*>(&g_Sh[o]) = hp;
                        *reinterpret_cast<uint32_t*>(&g_Sl[o]) = lp;
                    } else if constexpr (MODE == 4) {
                        uint32_t hp, lp;
                        split_pack(v0, v1, hp, lp);
                        size_t o = ((size_t)bz * TT + grow) * DD + gcol;
                        *reinterpret_cast<uint32_t*>(&g_valh[o]) = hp;
                        *reinterpret_cast<uint32_t*>(&g_vall[o]) = lp;
                    } else if constexpr (MODE == 5) {
                        v0 = fmaxf(v0 + bias[gcol], 0.f);
                        v1 = fmaxf(v1 + bias[gcol + 1], 0.f);
                        uint32_t hp, lp;
                        split_pack(v0, v1, hp, lp);
                        size_t o = (size_t)grow * DD + gcol;
                        *reinterpret_cast<uint32_t*>(&g_hh[o]) = hp;
                        *reinterpret_cast<uint32_t*>(&g_hl[o]) = lp;
                    } else if constexpr (MODE == 6) {
                        int b = grow >> 10, t = grow & 1023;
                        int L = vlen_of(vlen, b);
                        float valid = (t < L) ? 1.f : 0.f;
                        size_t o = (size_t)grow * DD + gcol;
                        float2 a2 = *reinterpret_cast<const float2*>(&xin[o]);
                        float g0 = valid / (1.f + expf(-(v0 + bias[gcol])));
                        float g1 = valid / (1.f + expf(-(v1 + bias[gcol + 1])));
                        uint32_t hp, lp;
                        split_pack(a2.x * g0 + a2.x, a2.y * g1 + a2.y, hp, lp);
                        *reinterpret_cast<uint32_t*>(&g_enhh[o]) = hp;
                        *reinterpret_cast<uint32_t*>(&g_enhl[o]) = lp;
                    } else {  // MODE 7
                        size_t o = (size_t)grow * DD + gcol;
                        float2 r2 = {v0 + bias[gcol], v1 + bias[gcol + 1]};
                        *reinterpret_cast<float2*>(&fout[o]) = r2;
                    }
                }
            }
    }
}

// =================== launch ================================================
extern "C" void kernel_launch(void* const* d_in, const int* in_sizes, int n_in,
                              void* d_out, int out_size) {
    const float* aud = (const float*)d_in[0];
    const float* vid = (const float*)d_in[1];
    const int*   vl  = (const int*)  d_in[2];
    const float* Wq  = (const float*)d_in[3];
    const float* bq  = (const float*)d_in[4];
    const float* Wk  = (const float*)d_in[5];
    const float* bk  = (const float*)d_in[6];
    const float* Wv  = (const float*)d_in[7];
    const float* bv  = (const float*)d_in[8];
    const float* Wc1 = (const float*)d_in[9];
    const float* bc1 = (const float*)d_in[10];
    const float* Wc2 = (const float*)d_in[11];
    const float* bc2 = (const float*)d_in[12];
    const float* Wf  = (const float*)d_in[13];
    const float* bf  = (const float*)d_in[14];
    float* out = (float*)d_out;

    const int SM = 196608;
    cudaFuncSetAttribute(gemm_kernel<0>, cudaFuncAttributeMaxDynamicSharedMemorySize, SM);
    cudaFuncSetAttribute(gemm_kernel<1>, cudaFuncAttributeMaxDynamicSharedMemorySize, SM);
    cudaFuncSetAttribute(gemm_kernel<2>, cudaFuncAttributeMaxDynamicSharedMemorySize, SM);
    cudaFuncSetAttribute(gemm_kernel<3>, cudaFuncAttributeMaxDynamicSharedMemorySize, SM);
    cudaFuncSetAttribute(gemm_kernel<4>, cudaFuncAttributeMaxDynamicSharedMemorySize, SM);
    cudaFuncSetAttribute(gemm_kernel<5>, cudaFuncAttributeMaxDynamicSharedMemorySize, SM);
    cudaFuncSetAttribute(gemm_kernel<6>, cudaFuncAttributeMaxDynamicSharedMemorySize, SM);
    cudaFuncSetAttribute(gemm_kernel<7>, cudaFuncAttributeMaxDynamicSharedMemorySize, SM);

    __nv_bfloat16 *wqh, *wql, *wkh, *wkl, *wvh, *wvl, *w1h, *w1l, *w2h, *w2l, *wfh, *wfl;
    cudaGetSymbolAddress((void**)&wqh, g_Wqth);
    cudaGetSymbolAddress((void**)&wql, g_Wqtl);
    cudaGetSymbolAddress((void**)&wkh, g_Wkth);
    cudaGetSymbolAddress((void**)&wkl, g_Wktl);
    cudaGetSymbolAddress((void**)&wvh, g_Wvth);
    cudaGetSymbolAddress((void**)&wvl, g_Wvtl);
    cudaGetSymbolAddress((void**)&w1h, g_Wc1th);
    cudaGetSymbolAddress((void**)&w1l, g_Wc1tl);
    cudaGetSymbolAddress((void**)&w2h, g_Wc2th);
    cudaGetSymbolAddress((void**)&w2l, g_Wc2tl);
    cudaGetSymbolAddress((void**)&wfh, g_Wfth);
    cudaGetSymbolAddress((void**)&wfl, g_Wftl);

    wtrans_kernel<<<dim3(16, 16), 256>>>(Wq, 512, 512, wqh, wql);
    wtrans_kernel<<<dim3(16, 16), 256>>>(Wk, 512, 512, wkh, wkl);
    wtrans_kernel<<<dim3(16, 16), 256>>>(Wv, 512, 512, wvh, wvl);
    wtrans_kernel<<<dim3(16, 48), 256>>>(Wc1, 1536, 512, w1h, w1l);
    wtrans_kernel<<<dim3(16, 16), 256>>>(Wc2, 512, 512, w2h, w2l);
    wtrans_kernel<<<dim3(16, 32), 256>>>(Wf, 1024, 512, wfh, wfl);

    gemm_kernel<0><<<dim3(2, 128), 256, SM>>>(bq, aud, vl, nullptr);
    gemm_kernel<1><<<dim3(2, 128), 256, SM>>>(bk, vid, vl, nullptr);
    gemm_kernel<2><<<dim3(2, 128), 256, SM>>>(bv, vid, vl, nullptr);
    gemm_kernel<3><<<dim3(4, 8, 16), 256, SM>>>(nullptr, nullptr, vl, nullptr);
    softmax_kernel<<<MTOT, 256>>>(vl);
    gemm_kernel<4><<<dim3(2, 8, 16), 256, SM>>>(nullptr, nullptr, vl, nullptr);
    gemm_kernel<5><<<dim3(2, 128), 256, SM>>>(bc1, nullptr, vl, nullptr);
    gemm_kernel<6><<<dim3(2, 128), 256, SM>>>(bc2, aud, vl, nullptr);
    gemm_kernel<7><<<dim3(2, 128), 256, SM>>>(bf, vid, vl, out);
}

// round 9
// speedup vs baseline: 3.4265x; 1.3208x over previous
#include <cuda_runtime.h>
#include <cuda_fp16.h>
#include <math.h>
#include <stdint.h>

// Problem constants
#define BB 16
#define TT 1024
#define DD 512
#define MTOT (BB * TT)                  // 16384
#define SCALE 0.04419417382415922f      // 1/sqrt(512)

// =================== helpers (plain sm_80+ features only) ==================
__device__ __forceinline__ uint32_t smem_u32_of(const void* p) {
    uint32_t a;
    asm("{ .reg .u64 t; cvta.to.shared.u64 t, %1; cvt.u32.u64 %0, t; }"
        : "=r"(a) : "l"(p));
    return a;
}
__device__ __forceinline__ void cpa16(uint32_t dst, const void* src) {
    asm volatile("cp.async.cg.shared.global [%0], [%1], 16;"
                 :: "r"(dst), "l"(src));
}
__device__ __forceinline__ void cpa16z(uint32_t dst, const void* src, int sz) {
    asm volatile("cp.async.cg.shared.global [%0], [%1], 16, %2;"
                 :: "r"(dst), "l"(src), "r"(sz));
}
#define CP_COMMIT() asm volatile("cp.async.commit_group;" ::: "memory")
#define CP_WAIT0()  asm volatile("cp.async.wait_group 0;" ::: "memory")

__device__ __forceinline__ void ldm4(uint32_t r[4], uint32_t addr) {
    asm volatile("ldmatrix.sync.aligned.m8n8.x4.shared.b16 {%0,%1,%2,%3}, [%4];"
                 : "=r"(r[0]), "=r"(r[1]), "=r"(r[2]), "=r"(r[3]) : "r"(addr));
}
#define MMA_F16(c, a, b0, b1)                                                  \
    asm volatile("mma.sync.aligned.m16n8k16.row.col.f32.f16.f16.f32 "          \
        "{%0,%1,%2,%3},{%4,%5,%6,%7},{%8,%9},{%0,%1,%2,%3};"                   \
        : "+f"((c)[0]), "+f"((c)[1]), "+f"((c)[2]), "+f"((c)[3])               \
        : "r"((a)[0]), "r"((a)[1]), "r"((a)[2]), "r"((a)[3]),                  \
          "r"(b0), "r"(b1))

__device__ __forceinline__ uint32_t sw128(uint32_t off) {
    return off ^ ((off >> 3) & 0x70);
}

// =================== scratch (fp16; ~151 MB) ===============================
__device__ __half g_Qh[MTOT * DD], g_Ql[MTOT * DD];       // Q pair (A side)
__device__ __half g_Kh[MTOT * DD];                        // K hi (B side)
__device__ __half g_Vth[MTOT * DD];                       // V^T hi [b][d][t]
__device__ __half g_Sh[BB * TT * TT], g_Sl[BB * TT * TT]; // logits->probs pair
// dead-buffer aliases (lifetimes verified disjoint):
//   val (PV out) reuses Q; h (conv1 out) hi reuses K, lo reuses Sh;
//   enh (gate out) hi reuses Vth, lo reuses Sl.
#define g_valh g_Qh
#define g_vall g_Ql
#define g_hh   g_Kh
#define g_hl   g_Sh
#define g_enhh g_Vth
#define g_enhl g_Sl
// transposed weights [N, K], hi plane only
__device__ __half g_Wqt[DD * DD];
__device__ __half g_Wkt[DD * DD];
__device__ __half g_Wvt[DD * DD];
__device__ __half g_Wc1t[DD * 1536];
__device__ __half g_Wc2t[DD * DD];
__device__ __half g_Wft[DD * 1024];

__device__ __forceinline__ void split2(float v, __half& h, __half& l) {
    h = __float2half(v);
    l = __float2half(v - __half2float(h));
}
__device__ __forceinline__ void split_pack(float v0, float v1,
                                           uint32_t& hp, uint32_t& lp) {
    __half h0, l0, h1, l1;
    split2(v0, h0, l0);
    split2(v1, h1, l1);
    hp = (uint32_t)__half_as_ushort(h0) | ((uint32_t)__half_as_ushort(h1) << 16);
    lp = (uint32_t)__half_as_ushort(l0) | ((uint32_t)__half_as_ushort(l1) << 16);
}
__device__ __forceinline__ int vlen_of(const int* __restrict__ vl, int b) {
    int stride = (vl[1] == 0) ? 2 : 1;   // int64 vs int32 (values in [1,1024])
    return vl[b * stride];
}

// =================== prep: weight transpose (hi plane only) ================
// W [K,N=512] fp32 -> T [N,K] fp16
__global__ __launch_bounds__(256)
void wtrans_kernel(const float* __restrict__ W, int K,
                   __half* __restrict__ T) {
    __shared__ float t[32][33];
    int n0 = blockIdx.x * 32, k0 = blockIdx.y * 32;
    int tx = threadIdx.x & 31, ty = threadIdx.x >> 5;
    for (int i = ty; i < 32; i += 8)
        t[i][tx] = W[(size_t)(k0 + i) * 512 + n0 + tx];
    __syncthreads();
    for (int i = ty; i < 32; i += 8)
        T[(size_t)(n0 + i) * K + k0 + tx] = __float2half(t[tx][i]);
}

// =================== masked softmax (in place on split logits) =============
__global__ __launch_bounds__(256)
void softmax_kernel(const int* __restrict__ vl) {
    __shared__ float red[8];
    int row = blockIdx.x;
    int b = row >> 10;
    int L = vlen_of(vl, b);
    size_t rbase = (size_t)row * TT;
    int tid = threadIdx.x, lane = tid & 31, wid = tid >> 5;
    int k0 = tid * 4;
    float xs[4];
#pragma unroll
    for (int c = 0; c < 4; c++)
        xs[c] = __half2float(g_Sh[rbase + k0 + c]) +
                __half2float(g_Sl[rbase + k0 + c]);
    float m = -3.4e38f;
#pragma unroll
    for (int c = 0; c < 4; c++)
        if (k0 + c < L) m = fmaxf(m, xs[c]);
#pragma unroll
    for (int s = 16; s > 0; s >>= 1)
        m = fmaxf(m, __shfl_xor_sync(0xffffffffu, m, s));
    if (lane == 0) red[wid] = m;
    __syncthreads();
    if (wid == 0) {
        float t = red[lane & 7];
#pragma unroll
        for (int s = 4; s > 0; s >>= 1)
            t = fmaxf(t, __shfl_xor_sync(0xffffffffu, t, s));
        if (lane == 0) red[0] = t;
    }
    __syncthreads();
    float rm = red[0];
    float e[4], sum = 0.f;
#pragma unroll
    for (int c = 0; c < 4; c++) {
        e[c] = (k0 + c < L) ? expf(xs[c] - rm) : 0.f;
        sum += e[c];
    }
#pragma unroll
    for (int s = 16; s > 0; s >>= 1)
        sum += __shfl_xor_sync(0xffffffffu, sum, s);
    __syncthreads();
    if (lane == 0) red[wid] = sum;
    __syncthreads();
    if (wid == 0) {
        float t = red[lane & 7];
#pragma unroll
        for (int s = 4; s > 0; s >>= 1)
            t += __shfl_xor_sync(0xffffffffu, t, s);
        if (lane == 0) red[0] = t;
    }
    __syncthreads();
    float inv = 1.f / red[0];
#pragma unroll
    for (int c = 0; c < 4; c++) {
        __half h, l;
        split2(e[c] * inv, h, l);
        g_Sh[rbase + k0 + c] = h;
        g_Sl[rbase + k0 + c] = l;
    }
}

// =================== mma.sync fp16x2 GEMM, 128x256 tiles, 2-stage ==========
// MODE: 0=Qproj 1=Kproj 2=Vproj(T out) 3=scores 4=PV 5=conv1 6=gate 7=final
// SMEM stage: [Ah 16K][Al 16K][Bh 32K] = 64 KB x2 stages = 128 KB
#define SA_H 0
#define SA_L 16384
#define SB_H 32768
#define STAGE_BYTES 65536

__device__ __forceinline__ void split8_sts(char* dh, char* dl, uint32_t so,
                                           const float* __restrict__ src) {
    float4 v0 = *reinterpret_cast<const float4*>(src);
    float4 v1 = *reinterpret_cast<const float4*>(src + 4);
    float xs[8] = {v0.x, v0.y, v0.z, v0.w, v1.x, v1.y, v1.z, v1.w};
    __half h[8], l[8];
#pragma unroll
    for (int c = 0; c < 8; c++) split2(xs[c], h[c], l[c]);
    *reinterpret_cast<uint4*>(dh + so) = *reinterpret_cast<uint4*>(h);
    *reinterpret_cast<uint4*>(dl + so) = *reinterpret_cast<uint4*>(l);
}

__device__ __forceinline__ void load_tileB(uint32_t sbase, int stage,
        const __half* __restrict__ Bh, int n0, int ldb, int kc, int tid) {
    uint32_t dh = sbase + stage * STAGE_BYTES + SB_H;
#pragma unroll
    for (int it = 0; it < 8; it++) {               // 256 rows x 8 float4-cols
        int idx = it * 256 + tid;
        int r = idx >> 3, c8 = idx & 7;
        size_t off = (size_t)(n0 + r) * ldb + kc * 64 + c8 * 8;
        uint32_t so = sw128((uint32_t)(r * 128 + c8 * 16));
        cpa16(dh + so, Bh + off);
    }
}

template <int MODE>
__device__ __forceinline__ void load_tileA(char* smem, uint32_t sbase, int stage,
        const __half* __restrict__ Ah, const __half* __restrict__ Al,
        const float* __restrict__ xin, int m0, int lda, int kc, int tid) {
    uint32_t dhu = sbase + stage * STAGE_BYTES + SA_H;
    uint32_t dlu = sbase + stage * STAGE_BYTES + SA_L;
    char* dhc = smem + stage * STAGE_BYTES + SA_H;
    char* dlc = smem + stage * STAGE_BYTES + SA_L;
#pragma unroll
    for (int it = 0; it < 4; it++) {               // 128 rows x 8 float4-cols
        int idx = it * 256 + tid;
        int r = idx >> 3, c8 = idx & 7;
        uint32_t so = sw128((uint32_t)(r * 128 + c8 * 16));
        if constexpr (MODE <= 2) {
            split8_sts(dhc, dlc, so, &xin[(size_t)(m0 + r) * DD + kc * 64 + c8 * 8]);
        } else if constexpr (MODE == 5) {
            int gr = m0 + r, b = gr >> 10, t = gr & 1023;
            int ts = t + (kc >> 3) - 1;
            int ok = ((unsigned)ts < (unsigned)TT) ? 16 : 0;
            int tsc = min(max(ts, 0), TT - 1);
            size_t off = (size_t)((b << 10) + tsc) * DD + (kc & 7) * 64 + c8 * 8;
            cpa16z(dhu + so, g_valh + off, ok);
            cpa16z(dlu + so, g_vall + off, ok);
        } else if constexpr (MODE == 7) {
            int gr = m0 + r;
            if (kc < 8) {
                size_t off = (size_t)gr * DD + kc * 64 + c8 * 8;
                cpa16(dhu + so, g_enhh + off);
                cpa16(dlu + so, g_enhl + off);
            } else {
                split8_sts(dhc, dlc, so,
                           &xin[(size_t)gr * DD + (kc - 8) * 64 + c8 * 8]);
            }
        } else {
            size_t off = (size_t)(m0 + r) * lda + kc * 64 + c8 * 8;
            cpa16(dhu + so, Ah + off);
            cpa16(dlu + so, Al + off);
        }
    }
}

template <int MODE>
__global__ __launch_bounds__(256)
void gemm_kernel(const float* __restrict__ bias, const float* __restrict__ xin,
                 const int* __restrict__ vlen, float* __restrict__ fout) {
    constexpr int KTOT = (MODE == 5) ? 1536 : ((MODE == 4 || MODE == 7) ? 1024 : 512);
    constexpr int KT = KTOT / 64;

    extern __shared__ char smem[];
    int tid = threadIdx.x, wid = tid >> 5, lane = tid & 31;
    int bx = blockIdx.x, by = blockIdx.y, bz = blockIdx.z;
    uint32_t sbase = smem_u32_of(smem);
    int m0 = by * 128, n0 = bx * 256;

    const __half *Ah = nullptr, *Al = nullptr, *Bh = nullptr;
    int lda = 512, ldb = 512;
    if constexpr (MODE == 0) { Bh = g_Wqt; }
    if constexpr (MODE == 1) { Bh = g_Wkt; }
    if constexpr (MODE == 2) { Bh = g_Wvt; }
    if constexpr (MODE == 3) {
        size_t bo = (size_t)bz * TT * DD;
        Ah = g_Qh + bo; Al = g_Ql + bo; Bh = g_Kh + bo;
    }
    if constexpr (MODE == 4) {
        Ah = g_Sh + (size_t)bz * TT * TT; Al = g_Sl + (size_t)bz * TT * TT; lda = 1024;
        Bh = g_Vth + (size_t)bz * DD * TT; ldb = 1024;
    }
    if constexpr (MODE == 5) { Bh = g_Wc1t; ldb = 1536; }
    if constexpr (MODE == 6) { Ah = g_hh; Al = g_hl; Bh = g_Wc2t; }
    if constexpr (MODE == 7) { Bh = g_Wft; ldb = 1024; }

    int wm = (wid & 1) * 64, wn = (wid >> 1) * 64;
    float acc[4][8][4];
#pragma unroll
    for (int i = 0; i < 4; i++)
#pragma unroll
        for (int j = 0; j < 8; j++)
#pragma unroll
            for (int c = 0; c < 4; c++) acc[i][j][c] = 0.f;

    load_tileA<MODE>(smem, sbase, 0, Ah, Al, xin, m0, lda, 0, tid);
    load_tileB(sbase, 0, Bh, n0, ldb, 0, tid);
    CP_COMMIT();

    int a_r = (lane & 7) + ((lane >> 3) & 1) * 8;
    int a_c = ((lane >> 4) & 1) * 16;
    int b_r = (lane & 7) + ((lane >> 4) & 1) * 8;
    int b_c = ((lane >> 3) & 1) * 16;

    for (int kt = 0; kt < KT; kt++) {
        int cur = kt & 1;
        CP_WAIT0();
        __syncthreads();
        if (kt + 1 < KT) {
            load_tileA<MODE>(smem, sbase, cur ^ 1, Ah, Al, xin, m0, lda, kt + 1, tid);
            load_tileB(sbase, cur ^ 1, Bh, n0, ldb, kt + 1, tid);
            CP_COMMIT();
        }
        uint32_t bufb = sbase + cur * STAGE_BYTES;
#pragma unroll
        for (int ks = 0; ks < 4; ks++) {
            int kb = ks * 32;
            uint32_t ahf[4][4], alf[4][4];
#pragma unroll
            for (int i = 0; i < 4; i++) {
                uint32_t so = sw128((uint32_t)((wm + i * 16 + a_r) * 128 + kb + a_c));
                ldm4(ahf[i], bufb + SA_H + so);
                ldm4(alf[i], bufb + SA_L + so);
            }
#pragma unroll
            for (int j2 = 0; j2 < 4; j2++) {
                uint32_t so = sw128((uint32_t)((wn + j2 * 16 + b_r) * 128 + kb + b_c));
                uint32_t tb[4];
                ldm4(tb, bufb + SB_H + so);
#pragma unroll
                for (int i = 0; i < 4; i++) {
                    MMA_F16(acc[i][2 * j2],     ahf[i], tb[0], tb[1]);
                    MMA_F16(acc[i][2 * j2],     alf[i], tb[0], tb[1]);
                    MMA_F16(acc[i][2 * j2 + 1], ahf[i], tb[2], tb[3]);
                    MMA_F16(acc[i][2 * j2 + 1], alf[i], tb[2], tb[3]);
                }
            }
        }
    }

    // ---------------- epilogue ----------------
    if constexpr (MODE == 2) {
        // V: stage fp32 in smem, then write V^T (hi plane only)
        __syncthreads();
        float* s = reinterpret_cast<float*>(smem);   // 128 x 264 fp32 = 135168 B
#pragma unroll
        for (int i = 0; i < 4; i++)
#pragma unroll
            for (int j = 0; j < 8; j++) {
                int r0 = wm + i * 16 + (lane >> 2);
                int c = wn + j * 8 + 2 * (lane & 3);
                s[r0 * 264 + c]           = acc[i][j][0] + bias[n0 + c];
                s[r0 * 264 + c + 1]       = acc[i][j][1] + bias[n0 + c + 1];
                s[(r0 + 8) * 264 + c]     = acc[i][j][2] + bias[n0 + c];
                s[(r0 + 8) * 264 + c + 1] = acc[i][j][3] + bias[n0 + c + 1];
            }
        __syncthreads();
        int d = tid;                      // 256 head-dims
        int b = m0 >> 10, t0 = m0 & 1023;
        size_t obase = ((size_t)b * DD + n0 + d) * TT + t0;
        for (int m = 0; m < 128; m += 8) {
            __half hb[8];
#pragma unroll
            for (int q = 0; q < 8; q++)
                hb[q] = __float2half(s[(m + q) * 264 + d]);
            *reinterpret_cast<uint4*>(&g_Vth[obase + m]) =
                *reinterpret_cast<uint4*>(hb);
        }
    } else {
#pragma unroll
        for (int i = 0; i < 4; i++)
#pragma unroll
            for (int j = 0; j < 8; j++)
#pragma unroll
                for (int half = 0; half < 2; half++) {
                    int grow = m0 + wm + i * 16 + (lane >> 2) + half * 8;
                    int gcol = n0 + wn + j * 8 + 2 * (lane & 3);
                    float v0 = acc[i][j][half * 2];
                    float v1 = acc[i][j][half * 2 + 1];
                    if constexpr (MODE == 0 || MODE == 1) {
                        v0 += bias[gcol]; v1 += bias[gcol + 1];
                        size_t o = (size_t)grow * DD + gcol;
                        if constexpr (MODE == 0) {
                            uint32_t hp, lp;
                            split_pack(v0, v1, hp, lp);
                            *reinterpret_cast<uint32_t*>(&g_Qh[o]) = hp;
                            *reinterpret_cast<uint32_t*>(&g_Ql[o]) = lp;
                        } else {
                            __half2 hv = {__float2half(v0), __float2half(v1)};
                            *reinterpret_cast<__half2*>(&g_Kh[o]) = hv;
                        }
                    } else if constexpr (MODE == 3) {
                        uint32_t hp, lp;
                        split_pack(v0 * SCALE, v1 * SCALE, hp, lp);
                        size_t o = ((size_t)bz * TT + grow) * TT + gcol;
                        *reinterpret_cast<uint32_t*>(&g_Sh[o]) = hp;
                        *reinterpret_cast<uint32_t*>(&g_Sl[o]) = lp;
                    } else if constexpr (MODE == 4) {
                        uint32_t hp, lp;
                        split_pack(v0, v1, hp, lp);
                        size_t o = ((size_t)bz * TT + grow) * DD + gcol;
                        *reinterpret_cast<uint32_t*>(&g_valh[o]) = hp;
                        *reinterpret_cast<uint32_t*>(&g_vall[o]) = lp;
                    } else if constexpr (MODE == 5) {
                        v0 = fmaxf(v0 + bias[gcol], 0.f);
                        v1 = fmaxf(v1 + bias[gcol + 1], 0.f);
                        uint32_t hp, lp;
                        split_pack(v0, v1, hp, lp);
                        size_t o = (size_t)grow * DD + gcol;
                        *reinterpret_cast<uint32_t*>(&g_hh[o]) = hp;
                        *reinterpret_cast<uint32_t*>(&g_hl[o]) = lp;
                    } else if constexpr (MODE == 6) {
                        int b = grow >> 10, t = grow & 1023;
                        int L = vlen_of(vlen, b);
                        float valid = (t < L) ? 1.f : 0.f;
                        size_t o = (size_t)grow * DD + gcol;
                        float2 a2 = *reinterpret_cast<const float2*>(&xin[o]);
                        float g0 = valid / (1.f + expf(-(v0 + bias[gcol])));
                        float g1 = valid / (1.f + expf(-(v1 + bias[gcol + 1])));
                        uint32_t hp, lp;
                        split_pack(a2.x * g0 + a2.x, a2.y * g1 + a2.y, hp, lp);
                        *reinterpret_cast<uint32_t*>(&g_enhh[o]) = hp;
                        *reinterpret_cast<uint32_t*>(&g_enhl[o]) = lp;
                    } else {  // MODE 7
                        size_t o = (size_t)grow * DD + gcol;
                        float2 r2 = {v0 + bias[gcol], v1 + bias[gcol + 1]};
                        *reinterpret_cast<float2*>(&fout[o]) = r2;
                    }
                }
    }
}

// =================== launch ================================================
extern "C" void kernel_launch(void* const* d_in, const int* in_sizes, int n_in,
                              void* d_out, int out_size) {
    const float* aud = (const float*)d_in[0];
    const float* vid = (const float*)d_in[1];
    const int*   vl  = (const int*)  d_in[2];
    const float* Wq  = (const float*)d_in[3];
    const float* bq  = (const float*)d_in[4];
    const float* Wk  = (const float*)d_in[5];
    const float* bk  = (const float*)d_in[6];
    const float* Wv  = (const float*)d_in[7];
    const float* bv  = (const float*)d_in[8];
    const float* Wc1 = (const float*)d_in[9];
    const float* bc1 = (const float*)d_in[10];
    const float* Wc2 = (const float*)d_in[11];
    const float* bc2 = (const float*)d_in[12];
    const float* Wf  = (const float*)d_in[13];
    const float* bf  = (const float*)d_in[14];
    float* out = (float*)d_out;

    const int SM = 147456;   // 2 stages x 64 KB + slack for V-transpose staging
    cudaFuncSetAttribute(gemm_kernel<0>, cudaFuncAttributeMaxDynamicSharedMemorySize, SM);
    cudaFuncSetAttribute(gemm_kernel<1>, cudaFuncAttributeMaxDynamicSharedMemorySize, SM);
    cudaFuncSetAttribute(gemm_kernel<2>, cudaFuncAttributeMaxDynamicSharedMemorySize, SM);
    cudaFuncSetAttribute(gemm_kernel<3>, cudaFuncAttributeMaxDynamicSharedMemorySize, SM);
    cudaFuncSetAttribute(gemm_kernel<4>, cudaFuncAttributeMaxDynamicSharedMemorySize, SM);
    cudaFuncSetAttribute(gemm_kernel<5>, cudaFuncAttributeMaxDynamicSharedMemorySize, SM);
    cudaFuncSetAttribute(gemm_kernel<6>, cudaFuncAttributeMaxDynamicSharedMemorySize, SM);
    cudaFuncSetAttribute(gemm_kernel<7>, cudaFuncAttributeMaxDynamicSharedMemorySize, SM);

    __half *wq, *wk, *wv, *w1, *w2, *wf;
    cudaGetSymbolAddress((void**)&wq, g_Wqt);
    cudaGetSymbolAddress((void**)&wk, g_Wkt);
    cudaGetSymbolAddress((void**)&wv, g_Wvt);
    cudaGetSymbolAddress((void**)&w1, g_Wc1t);
    cudaGetSymbolAddress((void**)&w2, g_Wc2t);
    cudaGetSymbolAddress((void**)&wf, g_Wft);

    wtrans_kernel<<<dim3(16, 16), 256>>>(Wq, 512, wq);
    wtrans_kernel<<<dim3(16, 16), 256>>>(Wk, 512, wk);
    wtrans_kernel<<<dim3(16, 16), 256>>>(Wv, 512, wv);
    wtrans_kernel<<<dim3(16, 48), 256>>>(Wc1, 1536, w1);
    wtrans_kernel<<<dim3(16, 16), 256>>>(Wc2, 512, w2);
    wtrans_kernel<<<dim3(16, 32), 256>>>(Wf, 1024, wf);

    gemm_kernel<0><<<dim3(2, 128), 256, SM>>>(bq, aud, vl, nullptr);
    gemm_kernel<1><<<dim3(2, 128), 256, SM>>>(bk, vid, vl, nullptr);
    gemm_kernel<2><<<dim3(2, 128), 256, SM>>>(bv, vid, vl, nullptr);
    gemm_kernel<3><<<dim3(4, 8, 16), 256, SM>>>(nullptr, nullptr, vl, nullptr);
    softmax_kernel<<<MTOT, 256>>>(vl);
    gemm_kernel<4><<<dim3(2, 8, 16), 256, SM>>>(nullptr, nullptr, vl, nullptr);
    gemm_kernel<5><<<dim3(2, 128), 256, SM>>>(bc1, nullptr, vl, nullptr);
    gemm_kernel<6><<<dim3(2, 128), 256, SM>>>(bc2, aud, vl, nullptr);
    gemm_kernel<7><<<dim3(2, 128), 256, SM>>>(bf, vid, vl, out);
}

// round 10
// speedup vs baseline: 4.7313x; 1.3808x over previous
#include <cuda_runtime.h>
#include <cuda_fp16.h>
#include <math.h>
#include <stdint.h>

// Problem constants
#define BB 16
#define TT 1024
#define DD 512
#define MTOT (BB * TT)                  // 16384
#define SCALE 0.04419417382415922f      // 1/sqrt(512)

// =================== helpers (plain sm_80+ features only) ==================
__device__ __forceinline__ uint32_t smem_u32_of(const void* p) {
    uint32_t a;
    asm("{ .reg .u64 t; cvta.to.shared.u64 t, %1; cvt.u32.u64 %0, t; }"
        : "=r"(a) : "l"(p));
    return a;
}
__device__ __forceinline__ void cpa16(uint32_t dst, const void* src) {
    asm volatile("cp.async.cg.shared.global [%0], [%1], 16;"
                 :: "r"(dst), "l"(src));
}
__device__ __forceinline__ void cpa16z(uint32_t dst, const void* src, int sz) {
    asm volatile("cp.async.cg.shared.global [%0], [%1], 16, %2;"
                 :: "r"(dst), "l"(src), "r"(sz));
}
#define CP_COMMIT() asm volatile("cp.async.commit_group;" ::: "memory")
#define CP_WAIT0()  asm volatile("cp.async.wait_group 0;" ::: "memory")

__device__ __forceinline__ void ldm4(uint32_t r[4], uint32_t addr) {
    asm volatile("ldmatrix.sync.aligned.m8n8.x4.shared.b16 {%0,%1,%2,%3}, [%4];"
                 : "=r"(r[0]), "=r"(r[1]), "=r"(r[2]), "=r"(r[3]) : "r"(addr));
}
#define MMA_F16(c, a, b0, b1)                                                  \
    asm volatile("mma.sync.aligned.m16n8k16.row.col.f32.f16.f16.f32 "          \
        "{%0,%1,%2,%3},{%4,%5,%6,%7},{%8,%9},{%0,%1,%2,%3};"                   \
        : "+f"((c)[0]), "+f"((c)[1]), "+f"((c)[2]), "+f"((c)[3])               \
        : "r"((a)[0]), "r"((a)[1]), "r"((a)[2]), "r"((a)[3]),                  \
          "r"(b0), "r"(b1))

__device__ __forceinline__ uint32_t sw128(uint32_t off) {
    return off ^ ((off >> 3) & 0x70);
}

// =================== scratch (fp16; ~151 MB) ===============================
__device__ __half g_Qh[MTOT * DD], g_Ql[MTOT * DD];       // Q pair (scores A)
__device__ __half g_Kh[MTOT * DD];                        // K hi (scores B)
__device__ __half g_Vth[MTOT * DD];                       // V^T hi [b][d][t]
__device__ __half g_Sh[BB * TT * TT], g_Sl[BB * TT * TT]; // logits pair -> probs hi
// dead-buffer aliases (lifetimes verified disjoint):
//   val (PV out, hi) reuses Qh; h (conv1 out, hi) reuses Kh;
//   enh (gate out, hi) reuses Vth. Ql/Sl dead after scores/softmax.
#define g_valh g_Qh
#define g_hh   g_Kh
#define g_enhh g_Vth
// transposed weights [N, K], hi plane only
__device__ __half g_Wqt[DD * DD];
__device__ __half g_Wkt[DD * DD];
__device__ __half g_Wvt[DD * DD];
__device__ __half g_Wc1t[DD * 1536];
__device__ __half g_Wc2t[DD * DD];
__device__ __half g_Wft[DD * 1024];

__device__ __forceinline__ void split2(float v, __half& h, __half& l) {
    h = __float2half(v);
    l = __float2half(v - __half2float(h));
}
__device__ __forceinline__ void split_pack(float v0, float v1,
                                           uint32_t& hp, uint32_t& lp) {
    __half h0, l0, h1, l1;
    split2(v0, h0, l0);
    split2(v1, h1, l1);
    hp = (uint32_t)__half_as_ushort(h0) | ((uint32_t)__half_as_ushort(h1) << 16);
    lp = (uint32_t)__half_as_ushort(l0) | ((uint32_t)__half_as_ushort(l1) << 16);
}
__device__ __forceinline__ int vlen_of(const int* __restrict__ vl, int b) {
    int stride = (vl[1] == 0) ? 2 : 1;   // int64 vs int32 (values in [1,1024])
    return vl[b * stride];
}

// =================== prep: all 6 weight transposes in one launch ===========
// W [K,N=512] fp32 -> T [N,K] fp16; z selects the weight.
__global__ __launch_bounds__(256)
void wtrans6_kernel(const float* __restrict__ W0, const float* __restrict__ W1,
                    const float* __restrict__ W2, const float* __restrict__ W3,
                    const float* __restrict__ W4, const float* __restrict__ W5,
                    __half* __restrict__ T0, __half* __restrict__ T1,
                    __half* __restrict__ T2, __half* __restrict__ T3,
                    __half* __restrict__ T4, __half* __restrict__ T5) {
    int z = blockIdx.z;
    const float* W = (z == 0) ? W0 : (z == 1) ? W1 : (z == 2) ? W2
                   : (z == 3) ? W3 : (z == 4) ? W4 : W5;
    __half* T = (z == 0) ? T0 : (z == 1) ? T1 : (z == 2) ? T2
              : (z == 3) ? T3 : (z == 4) ? T4 : T5;
    int K = (z == 3) ? 1536 : (z == 5) ? 1024 : 512;
    int k0 = blockIdx.y * 32;
    if (k0 >= K) return;                 // uniform per block
    __shared__ float t[32][33];
    int n0 = blockIdx.x * 32;
    int tx = threadIdx.x & 31, ty = threadIdx.x >> 5;
    for (int i = ty; i < 32; i += 8)
        t[i][tx] = W[(size_t)(k0 + i) * 512 + n0 + tx];
    __syncthreads();
    for (int i = ty; i < 32; i += 8)
        T[(size_t)(n0 + i) * K + k0 + tx] = __float2half(t[tx][i]);
}

// =================== masked softmax: logits pair -> probs hi ===============
__global__ __launch_bounds__(256)
void softmax_kernel(const int* __restrict__ vl) {
    __shared__ float red[8];
    int row = blockIdx.x;
    int b = row >> 10;
    int L = vlen_of(vl, b);
    size_t rbase = (size_t)row * TT;
    int tid = threadIdx.x, lane = tid & 31, wid = tid >> 5;
    int k0 = tid * 4;
    float xs[4];
#pragma unroll
    for (int c = 0; c < 4; c++)
        xs[c] = __half2float(g_Sh[rbase + k0 + c]) +
                __half2float(g_Sl[rbase + k0 + c]);
    float m = -3.4e38f;
#pragma unroll
    for (int c = 0; c < 4; c++)
        if (k0 + c < L) m = fmaxf(m, xs[c]);
#pragma unroll
    for (int s = 16; s > 0; s >>= 1)
        m = fmaxf(m, __shfl_xor_sync(0xffffffffu, m, s));
    if (lane == 0) red[wid] = m;
    __syncthreads();
    if (wid == 0) {
        float t = red[lane & 7];
#pragma unroll
        for (int s = 4; s > 0; s >>= 1)
            t = fmaxf(t, __shfl_xor_sync(0xffffffffu, t, s));
        if (lane == 0) red[0] = t;
    }
    __syncthreads();
    float rm = red[0];
    float e[4], sum = 0.f;
#pragma unroll
    for (int c = 0; c < 4; c++) {
        e[c] = (k0 + c < L) ? expf(xs[c] - rm) : 0.f;
        sum += e[c];
    }
#pragma unroll
    for (int s = 16; s > 0; s >>= 1)
        sum += __shfl_xor_sync(0xffffffffu, sum, s);
    __syncthreads();
    if (lane == 0) red[wid] = sum;
    __syncthreads();
    if (wid == 0) {
        float t = red[lane & 7];
#pragma unroll
        for (int s = 4; s > 0; s >>= 1)
            t += __shfl_xor_sync(0xffffffffu, t, s);
        if (lane == 0) red[0] = t;
    }
    __syncthreads();
    float inv = 1.f / red[0];
    __half hb[4];
#pragma unroll
    for (int c = 0; c < 4; c++)
        hb[c] = __float2half(e[c] * inv);
    *reinterpret_cast<uint2*>(&g_Sh[rbase + k0]) =
        *reinterpret_cast<uint2*>(hb);
}

// =================== mma.sync GEMM, 128x256 tiles, 2-stage =================
// MODE: 0=Qproj 1=Kproj 2=Vproj(T out) 3=scores(A dual) 4=PV 5=conv1 6=gate 7=final
// SMEM stage: [Ah 16K][Al 16K][Bh 32K] = 64 KB x2 stages = 128 KB
// (SA_L unused for single-plane modes.)
#define SA_H 0
#define SA_L 16384
#define SB_H 32768
#define STAGE_BYTES 65536

// 8 fp32 -> 8 fp16 hi, one 16B smem store
__device__ __forceinline__ void hi8_sts(char* dh, uint32_t so,
                                        const float* __restrict__ src) {
    float4 v0 = *reinterpret_cast<const float4*>(src);
    float4 v1 = *reinterpret_cast<const float4*>(src + 4);
    float xs[8] = {v0.x, v0.y, v0.z, v0.w, v1.x, v1.y, v1.z, v1.w};
    __half h[8];
#pragma unroll
    for (int c = 0; c < 8; c++) h[c] = __float2half(xs[c]);
    *reinterpret_cast<uint4*>(dh + so) = *reinterpret_cast<uint4*>(h);
}

__device__ __forceinline__ void load_tileB(uint32_t sbase, int stage,
        const __half* __restrict__ Bh, int n0, int ldb, int kc, int tid) {
    uint32_t dh = sbase + stage * STAGE_BYTES + SB_H;
#pragma unroll
    for (int it = 0; it < 8; it++) {               // 256 rows x 8 float4-cols
        int idx = it * 256 + tid;
        int r = idx >> 3, c8 = idx & 7;
        size_t off = (size_t)(n0 + r) * ldb + kc * 64 + c8 * 8;
        uint32_t so = sw128((uint32_t)(r * 128 + c8 * 16));
        cpa16(dh + so, Bh + off);
    }
}

template <int MODE>
__device__ __forceinline__ void load_tileA(char* smem, uint32_t sbase, int stage,
        const __half* __restrict__ Ah, const __half* __restrict__ Al,
        const float* __restrict__ xin, int m0, int lda, int kc, int tid) {
    uint32_t dhu = sbase + stage * STAGE_BYTES + SA_H;
    uint32_t dlu = sbase + stage * STAGE_BYTES + SA_L;
    char* dhc = smem + stage * STAGE_BYTES + SA_H;
#pragma unroll
    for (int it = 0; it < 4; it++) {               // 128 rows x 8 float4-cols
        int idx = it * 256 + tid;
        int r = idx >> 3, c8 = idx & 7;
        uint32_t so = sw128((uint32_t)(r * 128 + c8 * 16));
        if constexpr (MODE <= 2) {
            // fp32 input -> fp16 hi only
            hi8_sts(dhc, so, &xin[(size_t)(m0 + r) * DD + kc * 64 + c8 * 8]);
        } else if constexpr (MODE == 3) {
            // scores: A dual (Q hi+lo)
            size_t off = (size_t)(m0 + r) * lda + kc * 64 + c8 * 8;
            cpa16(dhu + so, Ah + off);
            cpa16(dlu + so, Al + off);
        } else if constexpr (MODE == 5) {
            int gr = m0 + r, b = gr >> 10, t = gr & 1023;
            int ts = t + (kc >> 3) - 1;
            int ok = ((unsigned)ts < (unsigned)TT) ? 16 : 0;
            int tsc = min(max(ts, 0), TT - 1);
            size_t off = (size_t)((b << 10) + tsc) * DD + (kc & 7) * 64 + c8 * 8;
            cpa16z(dhu + so, g_valh + off, ok);
        } else if constexpr (MODE == 7) {
            int gr = m0 + r;
            if (kc < 8) {
                size_t off = (size_t)gr * DD + kc * 64 + c8 * 8;
                cpa16(dhu + so, g_enhh + off);
            } else {
                hi8_sts(dhc, so, &xin[(size_t)gr * DD + (kc - 8) * 64 + c8 * 8]);
            }
        } else {
            // MODE 4 (P hi), MODE 6 (h hi)
            size_t off = (size_t)(m0 + r) * lda + kc * 64 + c8 * 8;
            cpa16(dhu + so, Ah + off);
        }
    }
}

template <int MODE>
__global__ __launch_bounds__(256)
void gemm_kernel(const float* __restrict__ bias, const float* __restrict__ xin,
                 const int* __restrict__ vlen, float* __restrict__ fout) {
    constexpr int KTOT = (MODE == 5) ? 1536 : ((MODE == 4 || MODE == 7) ? 1024 : 512);
    constexpr int KT = KTOT / 64;
    constexpr bool A_DUAL = (MODE == 3);

    extern __shared__ char smem[];
    int tid = threadIdx.x, wid = tid >> 5, lane = tid & 31;
    int bx = blockIdx.x, by = blockIdx.y, bz = blockIdx.z;
    uint32_t sbase = smem_u32_of(smem);
    int m0 = by * 128, n0 = bx * 256;

    const __half *Ah = nullptr, *Al = nullptr, *Bh = nullptr;
    int lda = 512, ldb = 512;
    if constexpr (MODE == 0) { Bh = g_Wqt; }
    if constexpr (MODE == 1) { Bh = g_Wkt; }
    if constexpr (MODE == 2) { Bh = g_Wvt; }
    if constexpr (MODE == 3) {
        size_t bo = (size_t)bz * TT * DD;
        Ah = g_Qh + bo; Al = g_Ql + bo; Bh = g_Kh + bo;
    }
    if constexpr (MODE == 4) {
        Ah = g_Sh + (size_t)bz * TT * TT; lda = 1024;
        Bh = g_Vth + (size_t)bz * DD * TT; ldb = 1024;
    }
    if constexpr (MODE == 5) { Bh = g_Wc1t; ldb = 1536; }
    if constexpr (MODE == 6) { Ah = g_hh; Bh = g_Wc2t; }
    if constexpr (MODE == 7) { Bh = g_Wft; ldb = 1024; }

    int wm = (wid & 1) * 64, wn = (wid >> 1) * 64;
    float acc[4][8][4];
#pragma unroll
    for (int i = 0; i < 4; i++)
#pragma unroll
        for (int j = 0; j < 8; j++)
#pragma unroll
            for (int c = 0; c < 4; c++) acc[i][j][c] = 0.f;

    load_tileA<MODE>(smem, sbase, 0, Ah, Al, xin, m0, lda, 0, tid);
    load_tileB(sbase, 0, Bh, n0, ldb, 0, tid);
    CP_COMMIT();

    int a_r = (lane & 7) + ((lane >> 3) & 1) * 8;
    int a_c = ((lane >> 4) & 1) * 16;
    int b_r = (lane & 7) + ((lane >> 4) & 1) * 8;
    int b_c = ((lane >> 3) & 1) * 16;

    for (int kt = 0; kt < KT; kt++) {
        int cur = kt & 1;
        CP_WAIT0();
        __syncthreads();
        if (kt + 1 < KT) {
            load_tileA<MODE>(smem, sbase, cur ^ 1, Ah, Al, xin, m0, lda, kt + 1, tid);
            load_tileB(sbase, cur ^ 1, Bh, n0, ldb, kt + 1, tid);
            CP_COMMIT();
        }
        uint32_t bufb = sbase + cur * STAGE_BYTES;
#pragma unroll
        for (int ks = 0; ks < 4; ks++) {
            int kb = ks * 32;
            uint32_t ahf[4][4], alf[4][4];
#pragma unroll
            for (int i = 0; i < 4; i++) {
                uint32_t so = sw128((uint32_t)((wm + i * 16 + a_r) * 128 + kb + a_c));
                ldm4(ahf[i], bufb + SA_H + so);
                if constexpr (A_DUAL) ldm4(alf[i], bufb + SA_L + so);
            }
#pragma unroll
            for (int j2 = 0; j2 < 4; j2++) {
                uint32_t so = sw128((uint32_t)((wn + j2 * 16 + b_r) * 128 + kb + b_c));
                uint32_t tb[4];
                ldm4(tb, bufb + SB_H + so);
#pragma unroll
                for (int i = 0; i < 4; i++) {
                    MMA_F16(acc[i][2 * j2],     ahf[i], tb[0], tb[1]);
                    MMA_F16(acc[i][2 * j2 + 1], ahf[i], tb[2], tb[3]);
                    if constexpr (A_DUAL) {
                        MMA_F16(acc[i][2 * j2],     alf[i], tb[0], tb[1]);
                        MMA_F16(acc[i][2 * j2 + 1], alf[i], tb[2], tb[3]);
                    }
                }
            }
        }
    }

    // ---------------- epilogue ----------------
    if constexpr (MODE == 2) {
        // V: stage fp32 in smem, then write V^T (hi plane only)
        __syncthreads();
        float* s = reinterpret_cast<float*>(smem);   // 128 x 264 fp32 = 135168 B
#pragma unroll
        for (int i = 0; i < 4; i++)
#pragma unroll
            for (int j = 0; j < 8; j++) {
                int r0 = wm + i * 16 + (lane >> 2);
                int c = wn + j * 8 + 2 * (lane & 3);
                s[r0 * 264 + c]           = acc[i][j][0] + bias[n0 + c];
                s[r0 * 264 + c + 1]       = acc[i][j][1] + bias[n0 + c + 1];
                s[(r0 + 8) * 264 + c]     = acc[i][j][2] + bias[n0 + c];
                s[(r0 + 8) * 264 + c + 1] = acc[i][j][3] + bias[n0 + c + 1];
            }
        __syncthreads();
        int d = tid;                      // 256 head-dims
        int b = m0 >> 10, t0 = m0 & 1023;
        size_t obase = ((size_t)b * DD + n0 + d) * TT + t0;
        for (int m = 0; m < 128; m += 8) {
            __half hb[8];
#pragma unroll
            for (int q = 0; q < 8; q++)
                hb[q] = __float2half(s[(m + q) * 264 + d]);
            *reinterpret_cast<uint4*>(&g_Vth[obase + m]) =
                *reinterpret_cast<uint4*>(hb);
        }
    } else {
#pragma unroll
        for (int i = 0; i < 4; i++)
#pragma unroll
            for (int j = 0; j < 8; j++)
#pragma unroll
                for (int half = 0; half < 2; half++) {
                    int grow = m0 + wm + i * 16 + (lane >> 2) + half * 8;
                    int gcol = n0 + wn + j * 8 + 2 * (lane & 3);
                    float v0 = acc[i][j][half * 2];
                    float v1 = acc[i][j][half * 2 + 1];
                    if constexpr (MODE == 0 || MODE == 1) {
                        v0 += bias[gcol]; v1 += bias[gcol + 1];
                        size_t o = (size_t)grow * DD + gcol;
                        if constexpr (MODE == 0) {
                            uint32_t hp, lp;
                            split_pack(v0, v1, hp, lp);
                            *reinterpret_cast<uint32_t*>(&g_Qh[o]) = hp;
                            *reinterpret_cast<uint32_t*>(&g_Ql[o]) = lp;
                        } else {
                            __half2 hv = {__float2half(v0), __float2half(v1)};
                            *reinterpret_cast<__half2*>(&g_Kh[o]) = hv;
                        }
                    } else if constexpr (MODE == 3) {
                        uint32_t hp, lp;
                        split_pack(v0 * SCALE, v1 * SCALE, hp, lp);
                        size_t o = ((size_t)bz * TT + grow) * TT + gcol;
                        *reinterpret_cast<uint32_t*>(&g_Sh[o]) = hp;
                        *reinterpret_cast<uint32_t*>(&g_Sl[o]) = lp;
                    } else if constexpr (MODE == 4) {
                        size_t o = ((size_t)bz * TT + grow) * DD + gcol;
                        __half2 hv = {__float2half(v0), __float2half(v1)};
                        *reinterpret_cast<__half2*>(&g_valh[o]) = hv;
                    } else if constexpr (MODE == 5) {
                        v0 = fmaxf(v0 + bias[gcol], 0.f);
                        v1 = fmaxf(v1 + bias[gcol + 1], 0.f);
                        size_t o = (size_t)grow * DD + gcol;
                        __half2 hv = {__float2half(v0), __float2half(v1)};
                        *reinterpret_cast<__half2*>(&g_hh[o]) = hv;
                    } else if constexpr (MODE == 6) {
                        int b = grow >> 10, t = grow & 1023;
                        int L = vlen_of(vlen, b);
                        float valid = (t < L) ? 1.f : 0.f;
                        size_t o = (size_t)grow * DD + gcol;
                        float2 a2 = *reinterpret_cast<const float2*>(&xin[o]);
                        float g0 = valid / (1.f + expf(-(v0 + bias[gcol])));
                        float g1 = valid / (1.f + expf(-(v1 + bias[gcol + 1])));
                        __half2 hv = {__float2half(a2.x * g0 + a2.x),
                                      __float2half(a2.y * g1 + a2.y)};
                        *reinterpret_cast<__half2*>(&g_enhh[o]) = hv;
                    } else {  // MODE 7
                        size_t o = (size_t)grow * DD + gcol;
                        float2 r2 = {v0 + bias[gcol], v1 + bias[gcol + 1]};
                        *reinterpret_cast<float2*>(&fout[o]) = r2;
                    }
                }
    }
}

// =================== launch ================================================
extern "C" void kernel_launch(void* const* d_in, const int* in_sizes, int n_in,
                              void* d_out, int out_size) {
    const float* aud = (const float*)d_in[0];
    const float* vid = (const float*)d_in[1];
    const int*   vl  = (const int*)  d_in[2];
    const float* Wq  = (const float*)d_in[3];
    const float* bq  = (const float*)d_in[4];
    const float* Wk  = (const float*)d_in[5];
    const float* bk  = (const float*)d_in[6];
    const float* Wv  = (const float*)d_in[7];
    const float* bv  = (const float*)d_in[8];
    const float* Wc1 = (const float*)d_in[9];
    const float* bc1 = (const float*)d_in[10];
    const float* Wc2 = (const float*)d_in[11];
    const float* bc2 = (const float*)d_in[12];
    const float* Wf  = (const float*)d_in[13];
    const float* bf  = (const float*)d_in[14];
    float* out = (float*)d_out;

    const int SM = 147456;   // 2 stages x 64 KB + slack for V-transpose staging
    cudaFuncSetAttribute(gemm_kernel<0>, cudaFuncAttributeMaxDynamicSharedMemorySize, SM);
    cudaFuncSetAttribute(gemm_kernel<1>, cudaFuncAttributeMaxDynamicSharedMemorySize, SM);
    cudaFuncSetAttribute(gemm_kernel<2>, cudaFuncAttributeMaxDynamicSharedMemorySize, SM);
    cudaFuncSetAttribute(gemm_kernel<3>, cudaFuncAttributeMaxDynamicSharedMemorySize, SM);
    cudaFuncSetAttribute(gemm_kernel<4>, cudaFuncAttributeMaxDynamicSharedMemorySize, SM);
    cudaFuncSetAttribute(gemm_kernel<5>, cudaFuncAttributeMaxDynamicSharedMemorySize, SM);
    cudaFuncSetAttribute(gemm_kernel<6>, cudaFuncAttributeMaxDynamicSharedMemorySize, SM);
    cudaFuncSetAttribute(gemm_kernel<7>, cudaFuncAttributeMaxDynamicSharedMemorySize, SM);

    __half *wq, *wk, *wv, *w1, *w2, *wf;
    cudaGetSymbolAddress((void**)&wq, g_Wqt);
    cudaGetSymbolAddress((void**)&wk, g_Wkt);
    cudaGetSymbolAddress((void**)&wv, g_Wvt);
    cudaGetSymbolAddress((void**)&w1, g_Wc1t);
    cudaGetSymbolAddress((void**)&w2, g_Wc2t);
    cudaGetSymbolAddress((void**)&wf, g_Wft);

    // one launch for all six transposes (z = weight id; y guarded per-K)
    wtrans6_kernel<<<dim3(16, 48, 6), 256>>>(Wq, Wk, Wv, Wc1, Wc2, Wf,
                                             wq, wk, wv, w1, w2, wf);

    gemm_kernel<0><<<dim3(2, 128), 256, SM>>>(bq, aud, vl, nullptr);
    gemm_kernel<1><<<dim3(2, 128), 256, SM>>>(bk, vid, vl, nullptr);
    gemm_kernel<2><<<dim3(2, 128), 256, SM>>>(bv, vid, vl, nullptr);
    gemm_kernel<3><<<dim3(4, 8, 16), 256, SM>>>(nullptr, nullptr, vl, nullptr);
    softmax_kernel<<<MTOT, 256>>>(vl);
    gemm_kernel<4><<<dim3(2, 8, 16), 256, SM>>>(nullptr, nullptr, vl, nullptr);
    gemm_kernel<5><<<dim3(2, 128), 256, SM>>>(bc1, nullptr, vl, nullptr);
    gemm_kernel<6><<<dim3(2, 128), 256, SM>>>(bc2, aud, vl, nullptr);
    gemm_kernel<7><<<dim3(2, 128), 256, SM>>>(bf, vid, vl, out);
}

// round 11
// speedup vs baseline: 5.3247x; 1.1254x over previous
#include <cuda_runtime.h>
#include <cuda_fp16.h>
#include <math.h>
#include <stdint.h>

// Problem constants
#define BB 16
#define TT 1024
#define DD 512
#define MTOT (BB * TT)                  // 16384
#define SCALE 0.04419417382415922f      // 1/sqrt(512)

// =================== helpers (plain sm_80+ features only) ==================
__device__ __forceinline__ uint32_t smem_u32_of(const void* p) {
    uint32_t a;
    asm("{ .reg .u64 t; cvta.to.shared.u64 t, %1; cvt.u32.u64 %0, t; }"
        : "=r"(a) : "l"(p));
    return a;
}
__device__ __forceinline__ void cpa16(uint32_t dst, const void* src) {
    asm volatile("cp.async.cg.shared.global [%0], [%1], 16;"
                 :: "r"(dst), "l"(src));
}
__device__ __forceinline__ void cpa16z(uint32_t dst, const void* src, int sz) {
    asm volatile("cp.async.cg.shared.global [%0], [%1], 16, %2;"
                 :: "r"(dst), "l"(src), "r"(sz));
}
#define CP_COMMIT() asm volatile("cp.async.commit_group;" ::: "memory")
#define CP_WAIT0()  asm volatile("cp.async.wait_group 0;" ::: "memory")
#define CP_WAIT1()  asm volatile("cp.async.wait_group 1;" ::: "memory")

__device__ __forceinline__ void ldm4(uint32_t r[4], uint32_t addr) {
    asm volatile("ldmatrix.sync.aligned.m8n8.x4.shared.b16 {%0,%1,%2,%3}, [%4];"
                 : "=r"(r[0]), "=r"(r[1]), "=r"(r[2]), "=r"(r[3]) : "r"(addr));
}
#define MMA_F16(c, a, b0, b1)                                                  \
    asm volatile("mma.sync.aligned.m16n8k16.row.col.f32.f16.f16.f32 "          \
        "{%0,%1,%2,%3},{%4,%5,%6,%7},{%8,%9},{%0,%1,%2,%3};"                   \
        : "+f"((c)[0]), "+f"((c)[1]), "+f"((c)[2]), "+f"((c)[3])               \
        : "r"((a)[0]), "r"((a)[1]), "r"((a)[2]), "r"((a)[3]),                  \
          "r"(b0), "r"(b1))

__device__ __forceinline__ uint32_t sw128(uint32_t off) {
    return off ^ ((off >> 3) & 0x70);
}

// =================== scratch (fp16; ~151 MB) ===============================
__device__ __half g_Qh[MTOT * DD], g_Ql[MTOT * DD];       // Q pair (scores A)
__device__ __half g_Kh[MTOT * DD];                        // K hi (scores B)
__device__ __half g_Vth[MTOT * DD];                       // V^T hi [b][d][t]
__device__ __half g_Sh[BB * TT * TT], g_Sl[BB * TT * TT]; // logits pair -> probs hi
// dead-buffer aliases (lifetimes verified disjoint)
#define g_valh g_Qh
#define g_hh   g_Kh
#define g_enhh g_Vth
// transposed weights [N, K], hi plane only
__device__ __half g_Wqt[DD * DD];
__device__ __half g_Wkt[DD * DD];
__device__ __half g_Wvt[DD * DD];
__device__ __half g_Wc1t[DD * 1536];
__device__ __half g_Wc2t[DD * DD];
__device__ __half g_Wft[DD * 1024];

__device__ __forceinline__ void split2(float v, __half& h, __half& l) {
    h = __float2half(v);
    l = __float2half(v - __half2float(h));
}
__device__ __forceinline__ void split_pack(float v0, float v1,
                                           uint32_t& hp, uint32_t& lp) {
    __half h0, l0, h1, l1;
    split2(v0, h0, l0);
    split2(v1, h1, l1);
    hp = (uint32_t)__half_as_ushort(h0) | ((uint32_t)__half_as_ushort(h1) << 16);
    lp = (uint32_t)__half_as_ushort(l0) | ((uint32_t)__half_as_ushort(l1) << 16);
}
__device__ __forceinline__ int vlen_of(const int* __restrict__ vl, int b) {
    int stride = (vl[1] == 0) ? 2 : 1;   // int64 vs int32 (values in [1,1024])
    return vl[b * stride];
}

// =================== prep: all 6 weight transposes in one launch ===========
__global__ __launch_bounds__(256)
void wtrans6_kernel(const float* __restrict__ W0, const float* __restrict__ W1,
                    const float* __restrict__ W2, const float* __restrict__ W3,
                    const float* __restrict__ W4, const float* __restrict__ W5,
                    __half* __restrict__ T0, __half* __restrict__ T1,
                    __half* __restrict__ T2, __half* __restrict__ T3,
                    __half* __restrict__ T4, __half* __restrict__ T5) {
    int z = blockIdx.z;
    const float* W = (z == 0) ? W0 : (z == 1) ? W1 : (z == 2) ? W2
                   : (z == 3) ? W3 : (z == 4) ? W4 : W5;
    __half* T = (z == 0) ? T0 : (z == 1) ? T1 : (z == 2) ? T2
              : (z == 3) ? T3 : (z == 4) ? T4 : T5;
    int K = (z == 3) ? 1536 : (z == 5) ? 1024 : 512;
    int k0 = blockIdx.y * 32;
    if (k0 >= K) return;
    __shared__ float t[32][33];
    int n0 = blockIdx.x * 32;
    int tx = threadIdx.x & 31, ty = threadIdx.x >> 5;
    for (int i = ty; i < 32; i += 8)
        t[i][tx] = W[(size_t)(k0 + i) * 512 + n0 + tx];
    __syncthreads();
    for (int i = ty; i < 32; i += 8)
        T[(size_t)(n0 + i) * K + k0 + tx] = __float2half(t[tx][i]);
}

// =================== masked softmax: logits pair -> probs hi ===============
__global__ __launch_bounds__(256)
void softmax_kernel(const int* __restrict__ vl) {
    __shared__ float red[8];
    int row = blockIdx.x;
    int b = row >> 10;
    int L = vlen_of(vl, b);
    size_t rbase = (size_t)row * TT;
    int tid = threadIdx.x, lane = tid & 31, wid = tid >> 5;
    int k0 = tid * 4;
    float xs[4];
#pragma unroll
    for (int c = 0; c < 4; c++)
        xs[c] = __half2float(g_Sh[rbase + k0 + c]) +
                __half2float(g_Sl[rbase + k0 + c]);
    float m = -3.4e38f;
#pragma unroll
    for (int c = 0; c < 4; c++)
        if (k0 + c < L) m = fmaxf(m, xs[c]);
#pragma unroll
    for (int s = 16; s > 0; s >>= 1)
        m = fmaxf(m, __shfl_xor_sync(0xffffffffu, m, s));
    if (lane == 0) red[wid] = m;
    __syncthreads();
    if (wid == 0) {
        float t = red[lane & 7];
#pragma unroll
        for (int s = 4; s > 0; s >>= 1)
            t = fmaxf(t, __shfl_xor_sync(0xffffffffu, t, s));
        if (lane == 0) red[0] = t;
    }
    __syncthreads();
    float rm = red[0];
    float e[4], sum = 0.f;
#pragma unroll
    for (int c = 0; c < 4; c++) {
        e[c] = (k0 + c < L) ? expf(xs[c] - rm) : 0.f;
        sum += e[c];
    }
#pragma unroll
    for (int s = 16; s > 0; s >>= 1)
        sum += __shfl_xor_sync(0xffffffffu, sum, s);
    __syncthreads();
    if (lane == 0) red[wid] = sum;
    __syncthreads();
    if (wid == 0) {
        float t = red[lane & 7];
#pragma unroll
        for (int s = 4; s > 0; s >>= 1)
            t += __shfl_xor_sync(0xffffffffu, t, s);
        if (lane == 0) red[0] = t;
    }
    __syncthreads();
    float inv = 1.f / red[0];
    __half hb[4];
#pragma unroll
    for (int c = 0; c < 4; c++)
        hb[c] = __float2half(e[c] * inv);
    *reinterpret_cast<uint2*>(&g_Sh[rbase + k0]) =
        *reinterpret_cast<uint2*>(hb);
}

// ============ mma.sync GEMM, 128x256 tiles, 512 threads, 3-stage ===========
// MODE: 0=Qproj 1=Kproj 2=Vproj(T out) 3=scores(A dual) 4=PV 5=conv1 6=gate 7=final
// SMEM stage: [Ah 16K][Al 16K][Bh 32K] = 64 KB x3 = 192 KB
#define SA_H 0
#define SA_L 16384
#define SB_H 32768
#define STAGE_BYTES 65536
#define NTHREADS 512

__device__ __forceinline__ void hi8_sts(char* dh, uint32_t so,
                                        const float* __restrict__ src) {
    float4 v0 = *reinterpret_cast<const float4*>(src);
    float4 v1 = *reinterpret_cast<const float4*>(src + 4);
    float xs[8] = {v0.x, v0.y, v0.z, v0.w, v1.x, v1.y, v1.z, v1.w};
    __half h[8];
#pragma unroll
    for (int c = 0; c < 8; c++) h[c] = __float2half(xs[c]);
    *reinterpret_cast<uint4*>(dh + so) = *reinterpret_cast<uint4*>(h);
}

__device__ __forceinline__ void load_tileB(uint32_t sbase, int stage,
        const __half* __restrict__ Bh, int n0, int ldb, int kc, int tid) {
    uint32_t dh = sbase + stage * STAGE_BYTES + SB_H;
#pragma unroll
    for (int it = 0; it < 4; it++) {               // 256 rows x 8 cols / 512 thr
        int idx = it * NTHREADS + tid;
        int r = idx >> 3, c8 = idx & 7;
        size_t off = (size_t)(n0 + r) * ldb + kc * 64 + c8 * 8;
        uint32_t so = sw128((uint32_t)(r * 128 + c8 * 16));
        cpa16(dh + so, Bh + off);
    }
}

template <int MODE>
__device__ __forceinline__ void load_tileA(char* smem, uint32_t sbase, int stage,
        const __half* __restrict__ Ah, const __half* __restrict__ Al,
        const float* __restrict__ xin, int m0, int lda, int kc, int tid) {
    uint32_t dhu = sbase + stage * STAGE_BYTES + SA_H;
    uint32_t dlu = sbase + stage * STAGE_BYTES + SA_L;
    char* dhc = smem + stage * STAGE_BYTES + SA_H;
#pragma unroll
    for (int it = 0; it < 2; it++) {               // 128 rows x 8 cols / 512 thr
        int idx = it * NTHREADS + tid;
        int r = idx >> 3, c8 = idx & 7;
        uint32_t so = sw128((uint32_t)(r * 128 + c8 * 16));
        if constexpr (MODE <= 2) {
            hi8_sts(dhc, so, &xin[(size_t)(m0 + r) * DD + kc * 64 + c8 * 8]);
        } else if constexpr (MODE == 3) {
            size_t off = (size_t)(m0 + r) * lda + kc * 64 + c8 * 8;
            cpa16(dhu + so, Ah + off);
            cpa16(dlu + so, Al + off);
        } else if constexpr (MODE == 5) {
            int gr = m0 + r, b = gr >> 10, t = gr & 1023;
            int ts = t + (kc >> 3) - 1;
            int ok = ((unsigned)ts < (unsigned)TT) ? 16 : 0;
            int tsc = min(max(ts, 0), TT - 1);
            size_t off = (size_t)((b << 10) + tsc) * DD + (kc & 7) * 64 + c8 * 8;
            cpa16z(dhu + so, g_valh + off, ok);
        } else if constexpr (MODE == 7) {
            int gr = m0 + r;
            if (kc < 8) {
                size_t off = (size_t)gr * DD + kc * 64 + c8 * 8;
                cpa16(dhu + so, g_enhh + off);
            } else {
                hi8_sts(dhc, so, &xin[(size_t)gr * DD + (kc - 8) * 64 + c8 * 8]);
            }
        } else {
            size_t off = (size_t)(m0 + r) * lda + kc * 64 + c8 * 8;
            cpa16(dhu + so, Ah + off);
        }
    }
}

template <int MODE>
__global__ __launch_bounds__(NTHREADS)
void gemm_kernel(const float* __restrict__ bias, const float* __restrict__ xin,
                 const int* __restrict__ vlen, float* __restrict__ fout) {
    constexpr int KTOT = (MODE == 5) ? 1536 : ((MODE == 4 || MODE == 7) ? 1024 : 512);
    constexpr int KT = KTOT / 64;
    constexpr bool A_DUAL = (MODE == 3);

    extern __shared__ char smem[];
    int tid = threadIdx.x, wid = tid >> 5, lane = tid & 31;
    int bx = blockIdx.x, by = blockIdx.y, bz = blockIdx.z;
    uint32_t sbase = smem_u32_of(smem);
    int m0 = by * 128, n0 = bx * 256;

    const __half *Ah = nullptr, *Al = nullptr, *Bh = nullptr;
    int lda = 512, ldb = 512;
    if constexpr (MODE == 0) { Bh = g_Wqt; }
    if constexpr (MODE == 1) { Bh = g_Wkt; }
    if constexpr (MODE == 2) { Bh = g_Wvt; }
    if constexpr (MODE == 3) {
        size_t bo = (size_t)bz * TT * DD;
        Ah = g_Qh + bo; Al = g_Ql + bo; Bh = g_Kh + bo;
    }
    if constexpr (MODE == 4) {
        Ah = g_Sh + (size_t)bz * TT * TT; lda = 1024;
        Bh = g_Vth + (size_t)bz * DD * TT; ldb = 1024;
    }
    if constexpr (MODE == 5) { Bh = g_Wc1t; ldb = 1536; }
    if constexpr (MODE == 6) { Ah = g_hh; Bh = g_Wc2t; }
    if constexpr (MODE == 7) { Bh = g_Wft; ldb = 1024; }

    // 16 warps: 4 (M) x 4 (N); warp tile 32x64
    int wm = (wid & 3) * 32, wn = (wid >> 2) * 64;
    float acc[2][8][4];
#pragma unroll
    for (int i = 0; i < 2; i++)
#pragma unroll
        for (int j = 0; j < 8; j++)
#pragma unroll
            for (int c = 0; c < 4; c++) acc[i][j][c] = 0.f;

    // prologue: chunks 0,1 -> stages 0,1
    load_tileA<MODE>(smem, sbase, 0, Ah, Al, xin, m0, lda, 0, tid);
    load_tileB(sbase, 0, Bh, n0, ldb, 0, tid);
    CP_COMMIT();
    load_tileA<MODE>(smem, sbase, 1, Ah, Al, xin, m0, lda, 1, tid);
    load_tileB(sbase, 1, Bh, n0, ldb, 1, tid);
    CP_COMMIT();

    int a_r = (lane & 7) + ((lane >> 3) & 1) * 8;
    int a_c = ((lane >> 4) & 1) * 16;
    int b_r = (lane & 7) + ((lane >> 4) & 1) * 8;
    int b_c = ((lane >> 3) & 1) * 16;

    int cur = 0;
    for (int kt = 0; kt < KT; kt++) {
        if (kt + 1 < KT) CP_WAIT1(); else CP_WAIT0();
        __syncthreads();
        if (kt + 2 < KT) {
            int nxt2 = cur + 2;
            if (nxt2 >= 3) nxt2 -= 3;
            load_tileA<MODE>(smem, sbase, nxt2, Ah, Al, xin, m0, lda, kt + 2, tid);
            load_tileB(sbase, nxt2, Bh, n0, ldb, kt + 2, tid);
            CP_COMMIT();
        }
        uint32_t bufb = sbase + cur * STAGE_BYTES;
#pragma unroll
        for (int ks = 0; ks < 4; ks++) {
            int kb = ks * 32;
            uint32_t ahf[2][4], alf[2][4];
#pragma unroll
            for (int i = 0; i < 2; i++) {
                uint32_t so = sw128((uint32_t)((wm + i * 16 + a_r) * 128 + kb + a_c));
                ldm4(ahf[i], bufb + SA_H + so);
                if constexpr (A_DUAL) ldm4(alf[i], bufb + SA_L + so);
            }
#pragma unroll
            for (int j2 = 0; j2 < 4; j2++) {
                uint32_t so = sw128((uint32_t)((wn + j2 * 16 + b_r) * 128 + kb + b_c));
                uint32_t tb[4];
                ldm4(tb, bufb + SB_H + so);
#pragma unroll
                for (int i = 0; i < 2; i++) {
                    MMA_F16(acc[i][2 * j2],     ahf[i], tb[0], tb[1]);
                    MMA_F16(acc[i][2 * j2 + 1], ahf[i], tb[2], tb[3]);
                    if constexpr (A_DUAL) {
                        MMA_F16(acc[i][2 * j2],     alf[i], tb[0], tb[1]);
                        MMA_F16(acc[i][2 * j2 + 1], alf[i], tb[2], tb[3]);
                    }
                }
            }
        }
        cur++;
        if (cur == 3) cur = 0;
    }

    // ---------------- epilogue ----------------
    if constexpr (MODE == 2) {
        // V: stage fp32 in smem, then write V^T (hi plane only)
        __syncthreads();
        float* s = reinterpret_cast<float*>(smem);   // 128 x 264 fp32 = 135168 B
#pragma unroll
        for (int i = 0; i < 2; i++)
#pragma unroll
            for (int j = 0; j < 8; j++) {
                int r0 = wm + i * 16 + (lane >> 2);
                int c = wn + j * 8 + 2 * (lane & 3);
                s[r0 * 264 + c]           = acc[i][j][0] + bias[n0 + c];
                s[r0 * 264 + c + 1]       = acc[i][j][1] + bias[n0 + c + 1];
                s[(r0 + 8) * 264 + c]     = acc[i][j][2] + bias[n0 + c];
                s[(r0 + 8) * 264 + c + 1] = acc[i][j][3] + bias[n0 + c + 1];
            }
        __syncthreads();
        int d = tid & 255;                // head-dim within tile
        int mh = (tid >> 8) * 64;         // half of the 128 m-rows
        int b = m0 >> 10, t0 = m0 & 1023;
        size_t obase = ((size_t)b * DD + n0 + d) * TT + t0 + mh;
        for (int m = 0; m < 64; m += 8) {
            __half hb[8];
#pragma unroll
            for (int q = 0; q < 8; q++)
                hb[q] = __float2half(s[(mh + m + q) * 264 + d]);
            *reinterpret_cast<uint4*>(&g_Vth[obase + m]) =
                *reinterpret_cast<uint4*>(hb);
        }
    } else {
#pragma unroll
        for (int i = 0; i < 2; i++)
#pragma unroll
            for (int j = 0; j < 8; j++)
#pragma unroll
                for (int half = 0; half < 2; half++) {
                    int grow = m0 + wm + i * 16 + (lane >> 2) + half * 8;
                    int gcol = n0 + wn + j * 8 + 2 * (lane & 3);
                    float v0 = acc[i][j][half * 2];
                    float v1 = acc[i][j][half * 2 + 1];
                    if constexpr (MODE == 0 || MODE == 1) {
                        v0 += bias[gcol]; v1 += bias[gcol + 1];
                        size_t o = (size_t)grow * DD + gcol;
                        if constexpr (MODE == 0) {
                            uint32_t hp, lp;
                            split_pack(v0, v1, hp, lp);
                            *reinterpret_cast<uint32_t*>(&g_Qh[o]) = hp;
                            *reinterpret_cast<uint32_t*>(&g_Ql[o]) = lp;
                        } else {
                            __half2 hv = {__float2half(v0), __float2half(v1)};
                            *reinterpret_cast<__half2*>(&g_Kh[o]) = hv;
                        }
                    } else if constexpr (MODE == 3) {
                        uint32_t hp, lp;
                        split_pack(v0 * SCALE, v1 * SCALE, hp, lp);
                        size_t o = ((size_t)bz * TT + grow) * TT + gcol;
                        *reinterpret_cast<uint32_t*>(&g_Sh[o]) = hp;
                        *reinterpret_cast<uint32_t*>(&g_Sl[o]) = lp;
                    } else if constexpr (MODE == 4) {
                        size_t o = ((size_t)bz * TT + grow) * DD + gcol;
                        __half2 hv = {__float2half(v0), __float2half(v1)};
                        *reinterpret_cast<__half2*>(&g_valh[o]) = hv;
                    } else if constexpr (MODE == 5) {
                        v0 = fmaxf(v0 + bias[gcol], 0.f);
                        v1 = fmaxf(v1 + bias[gcol + 1], 0.f);
                        size_t o = (size_t)grow * DD + gcol;
                        __half2 hv = {__float2half(v0), __float2half(v1)};
                        *reinterpret_cast<__half2*>(&g_hh[o]) = hv;
                    } else if constexpr (MODE == 6) {
                        int b = grow >> 10, t = grow & 1023;
                        int L = vlen_of(vlen, b);
                        float valid = (t < L) ? 1.f : 0.f;
                        size_t o = (size_t)grow * DD + gcol;
                        float2 a2 = *reinterpret_cast<const float2*>(&xin[o]);
                        float g0 = valid / (1.f + expf(-(v0 + bias[gcol])));
                        float g1 = valid / (1.f + expf(-(v1 + bias[gcol + 1])));
                        __half2 hv = {__float2half(a2.x * g0 + a2.x),
                                      __float2half(a2.y * g1 + a2.y)};
                        *reinterpret_cast<__half2*>(&g_enhh[o]) = hv;
                    } else {  // MODE 7
                        size_t o = (size_t)grow * DD + gcol;
                        float2 r2 = {v0 + bias[gcol], v1 + bias[gcol + 1]};
                        *reinterpret_cast<float2*>(&fout[o]) = r2;
                    }
                }
    }
}

// =================== launch ================================================
extern "C" void kernel_launch(void* const* d_in, const int* in_sizes, int n_in,
                              void* d_out, int out_size) {
    const float* aud = (const float*)d_in[0];
    const float* vid = (const float*)d_in[1];
    const int*   vl  = (const int*)  d_in[2];
    const float* Wq  = (const float*)d_in[3];
    const float* bq  = (const float*)d_in[4];
    const float* Wk  = (const float*)d_in[5];
    const float* bk  = (const float*)d_in[6];
    const float* Wv  = (const float*)d_in[7];
    const float* bv  = (const float*)d_in[8];
    const float* Wc1 = (const float*)d_in[9];
    const float* bc1 = (const float*)d_in[10];
    const float* Wc2 = (const float*)d_in[11];
    const float* bc2 = (const float*)d_in[12];
    const float* Wf  = (const float*)d_in[13];
    const float* bf  = (const float*)d_in[14];
    float* out = (float*)d_out;

    const int SM = 196608;   // 3 stages x 64 KB
    cudaFuncSetAttribute(gemm_kernel<0>, cudaFuncAttributeMaxDynamicSharedMemorySize, SM);
    cudaFuncSetAttribute(gemm_kernel<1>, cudaFuncAttributeMaxDynamicSharedMemorySize, SM);
    cudaFuncSetAttribute(gemm_kernel<2>, cudaFuncAttributeMaxDynamicSharedMemorySize, SM);
    cudaFuncSetAttribute(gemm_kernel<3>, cudaFuncAttributeMaxDynamicSharedMemorySize, SM);
    cudaFuncSetAttribute(gemm_kernel<4>, cudaFuncAttributeMaxDynamicSharedMemorySize, SM);
    cudaFuncSetAttribute(gemm_kernel<5>, cudaFuncAttributeMaxDynamicSharedMemorySize, SM);
    cudaFuncSetAttribute(gemm_kernel<6>, cudaFuncAttributeMaxDynamicSharedMemorySize, SM);
    cudaFuncSetAttribute(gemm_kernel<7>, cudaFuncAttributeMaxDynamicSharedMemorySize, SM);

    __half *wq, *wk, *wv, *w1, *w2, *wf;
    cudaGetSymbolAddress((void**)&wq, g_Wqt);
    cudaGetSymbolAddress((void**)&wk, g_Wkt);
    cudaGetSymbolAddress((void**)&wv, g_Wvt);
    cudaGetSymbolAddress((void**)&w1, g_Wc1t);
    cudaGetSymbolAddress((void**)&w2, g_Wc2t);
    cudaGetSymbolAddress((void**)&wf, g_Wft);

    wtrans6_kernel<<<dim3(16, 48, 6), 256>>>(Wq, Wk, Wv, Wc1, Wc2, Wf,
                                             wq, wk, wv, w1, w2, wf);

    gemm_kernel<0><<<dim3(2, 128), NTHREADS, SM>>>(bq, aud, vl, nullptr);
    gemm_kernel<1><<<dim3(2, 128), NTHREADS, SM>>>(bk, vid, vl, nullptr);
    gemm_kernel<2><<<dim3(2, 128), NTHREADS, SM>>>(bv, vid, vl, nullptr);
    gemm_kernel<3><<<dim3(4, 8, 16), NTHREADS, SM>>>(nullptr, nullptr, vl, nullptr);
    softmax_kernel<<<MTOT, 256>>>(vl);
    gemm_kernel<4><<<dim3(2, 8, 16), NTHREADS, SM>>>(nullptr, nullptr, vl, nullptr);
    gemm_kernel<5><<<dim3(2, 128), NTHREADS, SM>>>(bc1, nullptr, vl, nullptr);
    gemm_kernel<6><<<dim3(2, 128), NTHREADS, SM>>>(bc2, aud, vl, nullptr);
    gemm_kernel<7><<<dim3(2, 128), NTHREADS, SM>>>(bf, vid, vl, out);
}